// round 2
// baseline (speedup 1.0000x reference)
#include <cuda_runtime.h>
#include <cuda_bf16.h>

// Problem shape (from reference): B=8192, D=256, cats in [0,10), fonts unused.
#define B_MAX 8192
#define D_MAX 256

#define INV_T 1.4285714285714286f   // 1/0.7
#define M0    1.4285714285714286f   // fixed LSE shift: sims <= 1/0.7 for unit vectors

// Device scratch (allocation-free rule: __device__ globals)
__device__ float g_norm[B_MAX * D_MAX];   // L2-normalized embeddings, 8 MB
__device__ float g_pos [2 * B_MAX];       // per (j-chunk, row) hardest-positive sim
__device__ float g_negs[2 * B_MAX];       // per (j-chunk, row) sum exp(sim - M0) over negatives

// ---------------------------------------------------------------------------
// Kernel 1: row L2-normalize. One block (64 threads) per row, 1 float4/thread.
// ---------------------------------------------------------------------------
__global__ void k_normalize(const float* __restrict__ emb, int D) {
    int row = blockIdx.x;
    int t = threadIdx.x;                       // 0..63
    const float4* src = (const float4*)(emb + (size_t)row * D);
    float4 v = src[t];
    float ss = v.x * v.x + v.y * v.y + v.z * v.z + v.w * v.w;
    #pragma unroll
    for (int o = 16; o; o >>= 1) ss += __shfl_xor_sync(0xFFFFFFFFu, ss, o);
    __shared__ float sw[2];
    if ((t & 31) == 0) sw[t >> 5] = ss;
    __syncthreads();
    float tot = sw[0] + sw[1];
    float inv = 1.0f / fmaxf(sqrtf(tot), 1e-12f);
    float4 o4 = make_float4(v.x * inv, v.y * inv, v.z * inv, v.w * inv);
    ((float4*)(g_norm + (size_t)row * D))[t] = o4;
}

// ---------------------------------------------------------------------------
// Kernel 2: fused sims-GEMM + per-row masked max / sum-exp epilogue.
// Block tile: BM=128 rows x BN=128 cols, 256 threads, 8x8 per thread.
// blockIdx.x -> i-tile, blockIdx.y -> j-chunk (B/NJ columns each).
// ---------------------------------------------------------------------------
#define BM 128
#define BN 128
#define BK 16
#define TM 8
#define TN 8

__global__ void __launch_bounds__(256, 2)
k_main(const int* __restrict__ cat, int B, int D, int jChunk) {
    __shared__ float sA[BK * BM];
    __shared__ float sB[BK * BN];
    __shared__ int   sCat[BN];
    __shared__ float sRed[BM * 16];

    int tid = threadIdx.x;
    int tx = tid & 15;       // col group 0..15
    int ty = tid >> 4;       // row group 0..15
    int rowBase = blockIdx.x * BM;
    int jStart  = blockIdx.y * jChunk;

    float posm[TM], negs[TM];
    int ci[TM];
    #pragma unroll
    for (int i = 0; i < TM; i++) {
        posm[i] = -1e30f;
        negs[i] = 0.0f;
        ci[i]   = cat[rowBase + ty * TM + i];
    }

    for (int jt = jStart; jt < jStart + jChunk; jt += BN) {
        if (tid < BN) sCat[tid] = cat[jt + tid];

        float acc[TM][TN];
        #pragma unroll
        for (int i = 0; i < TM; i++)
            #pragma unroll
            for (int j = 0; j < TN; j++) acc[i][j] = 0.0f;

        for (int kt = 0; kt < D; kt += BK) {
            __syncthreads();
            // load 128x16 A and B slabs (transposed into smem as [k][m])
            #pragma unroll
            for (int s = 0; s < 2; s++) {
                int lin = tid + s * 256;        // 0..511
                int m = lin >> 2;               // 0..127
                int kq = (lin & 3) * 4;         // 0,4,8,12
                float4 va = *(const float4*)(g_norm + (size_t)(rowBase + m) * D + kt + kq);
                sA[(kq + 0) * BM + m] = va.x;
                sA[(kq + 1) * BM + m] = va.y;
                sA[(kq + 2) * BM + m] = va.z;
                sA[(kq + 3) * BM + m] = va.w;
                float4 vb = *(const float4*)(g_norm + (size_t)(jt + m) * D + kt + kq);
                sB[(kq + 0) * BN + m] = vb.x;
                sB[(kq + 1) * BN + m] = vb.y;
                sB[(kq + 2) * BN + m] = vb.z;
                sB[(kq + 3) * BN + m] = vb.w;
            }
            __syncthreads();
            #pragma unroll
            for (int k = 0; k < BK; k++) {
                float a[TM], b[TN];
                #pragma unroll
                for (int i = 0; i < TM; i++) a[i] = sA[k * BM + ty * TM + i];
                #pragma unroll
                for (int j = 0; j < TN; j++) b[j] = sB[k * BN + tx * TN + j];
                #pragma unroll
                for (int i = 0; i < TM; i++)
                    #pragma unroll
                    for (int j = 0; j < TN; j++)
                        acc[i][j] = fmaf(a[i], b[j], acc[i][j]);
            }
        }

        // epilogue: branchless masked reductions with fixed LSE shift M0
        #pragma unroll
        for (int j = 0; j < TN; j++) {
            int jg = jt + tx * TN + j;
            int cj = sCat[tx * TN + j];
            #pragma unroll
            for (int i = 0; i < TM; i++) {
                float sim = acc[i][j] * INV_T;
                bool same = (ci[i] == cj);
                float e = __expf(sim - M0);
                if (!same) {
                    negs[i] += e;
                } else if (jg != rowBase + ty * TM + i) {
                    posm[i] = fmaxf(posm[i], sim);
                }
            }
        }
        __syncthreads();   // protect sCat before next tile's reload
    }

    // reduce across the 16 tx-threads sharing each row
    #pragma unroll
    for (int i = 0; i < TM; i++) sRed[(ty * TM + i) * 16 + tx] = posm[i];
    __syncthreads();
    if (tid < BM) {
        float p = -1e30f;
        #pragma unroll
        for (int x = 0; x < 16; x++) p = fmaxf(p, sRed[tid * 16 + x]);
        g_pos[blockIdx.y * B + rowBase + tid] = p;
    }
    __syncthreads();
    #pragma unroll
    for (int i = 0; i < TM; i++) sRed[(ty * TM + i) * 16 + tx] = negs[i];
    __syncthreads();
    if (tid < BM) {
        float s = 0.0f;
        #pragma unroll
        for (int x = 0; x < 16; x++) s += sRed[tid * 16 + x];
        g_negs[blockIdx.y * B + rowBase + tid] = s;
    }
}

// ---------------------------------------------------------------------------
// Kernel 3: deterministic merge over j-chunks + per-row loss + mean.
// ---------------------------------------------------------------------------
__global__ void k_final(float* __restrict__ out, int B, int nj) {
    int tid = threadIdx.x;   // 256 threads, 1 block
    float sum = 0.0f, cnt = 0.0f;
    for (int r = tid; r < B; r += 256) {
        float p = -1e30f, ns = 0.0f;
        for (int c = 0; c < nj; c++) {
            p = fmaxf(p, g_pos[c * B + r]);
            ns += g_negs[c * B + r];
        }
        bool valid = (p > -1e29f) && (ns > 0.0f);
        if (valid) {
            float lse = M0 + logf(expf(p - M0) + ns);
            sum += (lse - p);
            cnt += 1.0f;
        }
    }
    __shared__ float ss[256], sc[256];
    ss[tid] = sum; sc[tid] = cnt;
    __syncthreads();
    for (int o = 128; o; o >>= 1) {
        if (tid < o) { ss[tid] += ss[tid + o]; sc[tid] += sc[tid + o]; }
        __syncthreads();
    }
    if (tid == 0) out[0] = (sc[0] > 0.0f) ? (ss[0] / sc[0]) : 0.0f;
}

// ---------------------------------------------------------------------------
extern "C" void kernel_launch(void* const* d_in, const int* in_sizes, int n_in,
                              void* d_out, int out_size) {
    const float* emb = (const float*)d_in[0];
    const int*   cat = (const int*)d_in[1];   // int64 in reference, int32 on the wire
    // d_in[2] = font_labels, unused by the reference loss
    int B = in_sizes[1];            // 8192
    int D = in_sizes[0] / B;        // 256

    k_normalize<<<B, 64>>>(emb, D);

    const int NJ = 2;               // j-chunks per row-tile -> 64*2 = 128 blocks (one wave)
    dim3 grid(B / BM, NJ);
    k_main<<<grid, 256>>>(cat, B, D, B / NJ);

    k_final<<<1, 256>>>((float*)d_out, B, NJ);
}

// round 3
// speedup vs baseline: 3.8916x; 3.8916x over previous
#include <cuda_runtime.h>
#include <cuda_bf16.h>
#include <cstdint>

// B=8192, D=256, categories int32 on the wire.
#define BDIM  8192
#define DDIM  256

#define INV_T 1.4285714285714286f   // 1/0.7
#define M0    1.4285714285714286f   // fixed LSE shift: sims <= 1/0.7 for unit vectors

#define BM  128
#define BN  128
#define BK  32
#define NJT 8                       // j-tiles per block
#define NJC (BDIM / (BN * NJT))     // 8 j-chunks

// smem layout constants (floats)
#define SA_STRIDE 260               // 256 + 4 pad  -> bank = (4*row + k) % 32, conflict-free frags
#define SB_STRIDE 36                // 32 + 4 pad
#define SA_WORDS  (BM * SA_STRIDE)          // 33280
#define SB_WORDS  (BM * SB_STRIDE)          // 4608 per buffer
#define SMEM_WORDS (SA_WORDS + 2 * SB_WORDS + BM + BM * 8)
#define SMEM_BYTES (SMEM_WORDS * 4)         // 174592 B

// Device scratch (allocation-free rule)
__device__ float g_norm[BDIM * DDIM];       // tf32-rounded normalized embeddings
__device__ float g_pos [NJC * BDIM];
__device__ float g_negs[NJC * BDIM];

__device__ __forceinline__ float to_tf32(float x) {
    uint32_t u;
    asm("cvt.rna.tf32.f32 %0, %1;" : "=r"(u) : "f"(x));
    return __uint_as_float(u);
}

__device__ __forceinline__ void mma_tf32(float d[4], const uint32_t a[4],
                                         uint32_t b0, uint32_t b1) {
    asm volatile(
        "mma.sync.aligned.m16n8k8.row.col.f32.tf32.tf32.f32 "
        "{%0,%1,%2,%3}, {%4,%5,%6,%7}, {%8,%9}, {%0,%1,%2,%3};\n"
        : "+f"(d[0]), "+f"(d[1]), "+f"(d[2]), "+f"(d[3])
        : "r"(a[0]), "r"(a[1]), "r"(a[2]), "r"(a[3]), "r"(b0), "r"(b1));
}

// ---------------------------------------------------------------------------
// Kernel 1: row L2-normalize + tf32 pre-round. One block (64 thr) per row.
// ---------------------------------------------------------------------------
__global__ void k_normalize(const float* __restrict__ emb) {
    int row = blockIdx.x;
    int t = threadIdx.x;                       // 0..63
    const float4* src = (const float4*)(emb + (size_t)row * DDIM);
    float4 v = src[t];
    float ss = v.x * v.x + v.y * v.y + v.z * v.z + v.w * v.w;
    #pragma unroll
    for (int o = 16; o; o >>= 1) ss += __shfl_xor_sync(0xFFFFFFFFu, ss, o);
    __shared__ float sw[2];
    if ((t & 31) == 0) sw[t >> 5] = ss;
    __syncthreads();
    float tot = sw[0] + sw[1];
    float inv = 1.0f / fmaxf(sqrtf(tot), 1e-12f);
    float4 o4 = make_float4(to_tf32(v.x * inv), to_tf32(v.y * inv),
                            to_tf32(v.z * inv), to_tf32(v.w * inv));
    ((float4*)(g_norm + (size_t)row * DDIM))[t] = o4;
}

// ---------------------------------------------------------------------------
// Kernel 2: tf32 tensor-core sims GEMM fused with masked max / sum-exp.
// Block: 256 threads (8 warps, 4 in M x 2 in N). A tile (128 x 256) resident
// in SMEM; B streamed in double-buffered 32-wide k-chunks over 8 j-tiles.
// ---------------------------------------------------------------------------
__global__ void __launch_bounds__(256, 1)
k_mma(const int* __restrict__ cat) {
    extern __shared__ float sm[];
    float*    sA   = sm;
    float*    sB   = sA + SA_WORDS;           // two buffers of SB_WORDS
    int*      sCat = (int*)(sB + 2 * SB_WORDS);
    float*    sRed = (float*)(sCat + BM);

    const int tid  = threadIdx.x;
    const int lane = tid & 31;
    const int warp = tid >> 5;
    const int wm   = warp & 3;                // M-group (32 rows)
    const int wn   = warp >> 2;               // N-group (64 cols)
    const int l4   = lane >> 2;               // 0..7
    const int lm   = lane & 3;                // 0..3
    const int rowBase = blockIdx.x * BM;

    // ---- load full A tile (128 x 256) into smem ----
    #pragma unroll
    for (int s = 0; s < 32; s++) {
        int idx = tid + s * 256;              // 8192 float4 slots
        int r = idx >> 6;                     // 64 float4 per row
        int q = idx & 63;
        float4 v = *(const float4*)(g_norm + (size_t)(rowBase + r) * DDIM + q * 4);
        *(float4*)(sA + r * SA_STRIDE + q * 4) = v;
    }

    // per-thread row categories + running reductions: rows = rowBase + wm*32 + mf*16 + h*8 + l4
    int   ci  [2][2];
    float posm[2][2], negs[2][2];
    #pragma unroll
    for (int mf = 0; mf < 2; mf++)
        #pragma unroll
        for (int h = 0; h < 2; h++) {
            ci[mf][h]   = cat[rowBase + wm * 32 + mf * 16 + h * 8 + l4];
            posm[mf][h] = -1e30f;
            negs[mf][h] = 0.0f;
        }

    const uint32_t* sAu = (const uint32_t*)sA;

    for (int jj = 0; jj < NJT; jj++) {
        const int jt = (blockIdx.y * NJT + jj) * BN;
        __syncthreads();                      // prior epilogue done with sCat / sB
        if (tid < BM) sCat[tid] = cat[jt + tid];

        float acc[2][8][4];
        #pragma unroll
        for (int mf = 0; mf < 2; mf++)
            #pragma unroll
            for (int nf = 0; nf < 8; nf++)
                #pragma unroll
                for (int c = 0; c < 4; c++) acc[mf][nf][c] = 0.0f;

        // prologue: stage B chunk 0
        float4 breg[4];
        #pragma unroll
        for (int t = 0; t < 4; t++) {
            int idx = tid + t * 256;          // 1024 float4
            int r = idx >> 3, q = idx & 7;
            breg[t] = *(const float4*)(g_norm + (size_t)(jt + r) * DDIM + 0 + q * 4);
        }
        #pragma unroll
        for (int t = 0; t < 4; t++) {
            int idx = tid + t * 256;
            int r = idx >> 3, q = idx & 7;
            *(float4*)(sB + r * SB_STRIDE + q * 4) = breg[t];
        }
        __syncthreads();

        int cur = 0;
        for (int kc = 0; kc < DDIM / BK; kc++) {
            if (kc < DDIM / BK - 1) {
                int kn = (kc + 1) * BK;
                #pragma unroll
                for (int t = 0; t < 4; t++) {
                    int idx = tid + t * 256;
                    int r = idx >> 3, q = idx & 7;
                    breg[t] = *(const float4*)(g_norm + (size_t)(jt + r) * DDIM + kn + q * 4);
                }
            }
            const uint32_t* sBu = (const uint32_t*)(sB + cur * SB_WORDS);

            #pragma unroll
            for (int ks = 0; ks < BK / 8; ks++) {
                const int kg = kc * BK + ks * 8;
                uint32_t a[2][4];
                #pragma unroll
                for (int mf = 0; mf < 2; mf++) {
                    int ao = (wm * 32 + mf * 16 + l4) * SA_STRIDE + kg + lm;
                    a[mf][0] = sAu[ao];
                    a[mf][1] = sAu[ao + 8 * SA_STRIDE];
                    a[mf][2] = sAu[ao + 4];
                    a[mf][3] = sAu[ao + 8 * SA_STRIDE + 4];
                }
                #pragma unroll
                for (int nf = 0; nf < 8; nf++) {
                    int bo = (wn * 64 + nf * 8 + l4) * SB_STRIDE + ks * 8 + lm;
                    uint32_t b0 = sBu[bo];
                    uint32_t b1 = sBu[bo + 4];
                    mma_tf32(acc[0][nf], a[0], b0, b1);
                    mma_tf32(acc[1][nf], a[1], b0, b1);
                }
            }

            if (kc < DDIM / BK - 1) {
                float* dst = sB + (cur ^ 1) * SB_WORDS;
                #pragma unroll
                for (int t = 0; t < 4; t++) {
                    int idx = tid + t * 256;
                    int r = idx >> 3, q = idx & 7;
                    *(float4*)(dst + r * SB_STRIDE + q * 4) = breg[t];
                }
                __syncthreads();
                cur ^= 1;
            }
        }

        // ---- fused epilogue: masked hardest-positive max + sum exp(sim - M0) over negs ----
        #pragma unroll
        for (int nf = 0; nf < 8; nf++) {
            int col0 = wn * 64 + nf * 8 + lm * 2;
            int cj0 = sCat[col0], cj1 = sCat[col0 + 1];
            int jg0 = jt + col0;
            #pragma unroll
            for (int mf = 0; mf < 2; mf++) {
                #pragma unroll
                for (int h = 0; h < 2; h++) {
                    int rg = rowBase + wm * 32 + mf * 16 + h * 8 + l4;
                    int cir = ci[mf][h];
                    float s0 = acc[mf][nf][2 * h + 0] * INV_T;
                    float s1 = acc[mf][nf][2 * h + 1] * INV_T;
                    float e0 = __expf(s0 - M0);
                    float e1 = __expf(s1 - M0);
                    if (cir != cj0)            negs[mf][h] += e0;
                    else if (jg0 != rg)        posm[mf][h] = fmaxf(posm[mf][h], s0);
                    if (cir != cj1)            negs[mf][h] += e1;
                    else if (jg0 + 1 != rg)    posm[mf][h] = fmaxf(posm[mf][h], s1);
                }
            }
        }
    }

    // ---- cross-thread reduction: 8 contributors per row (2 warp_n x 4 lane%4) ----
    __syncthreads();
    #pragma unroll
    for (int mf = 0; mf < 2; mf++)
        #pragma unroll
        for (int h = 0; h < 2; h++) {
            int rl = wm * 32 + mf * 16 + h * 8 + l4;
            sRed[rl * 8 + wn * 4 + lm] = posm[mf][h];
        }
    __syncthreads();
    if (tid < BM) {
        float p = -1e30f;
        #pragma unroll
        for (int x = 0; x < 8; x++) p = fmaxf(p, sRed[tid * 8 + x]);
        g_pos[blockIdx.y * BDIM + rowBase + tid] = p;
    }
    __syncthreads();
    #pragma unroll
    for (int mf = 0; mf < 2; mf++)
        #pragma unroll
        for (int h = 0; h < 2; h++) {
            int rl = wm * 32 + mf * 16 + h * 8 + l4;
            sRed[rl * 8 + wn * 4 + lm] = negs[mf][h];
        }
    __syncthreads();
    if (tid < BM) {
        float s = 0.0f;
        #pragma unroll
        for (int x = 0; x < 8; x++) s += sRed[tid * 8 + x];
        g_negs[blockIdx.y * BDIM + rowBase + tid] = s;
    }
}

// ---------------------------------------------------------------------------
// Kernel 3: deterministic merge over j-chunks + per-row loss + mean.
// ---------------------------------------------------------------------------
__global__ void k_final(float* __restrict__ out) {
    int tid = threadIdx.x;   // 256 threads, 1 block
    float sum = 0.0f, cnt = 0.0f;
    for (int r = tid; r < BDIM; r += 256) {
        float p = -1e30f, ns = 0.0f;
        #pragma unroll
        for (int c = 0; c < NJC; c++) {
            p = fmaxf(p, g_pos[c * BDIM + r]);
            ns += g_negs[c * BDIM + r];
        }
        bool valid = (p > -1e29f) && (ns > 0.0f);
        if (valid) {
            float lse = M0 + logf(expf(p - M0) + ns);
            sum += (lse - p);
            cnt += 1.0f;
        }
    }
    __shared__ float ss[256], sc[256];
    ss[tid] = sum; sc[tid] = cnt;
    __syncthreads();
    for (int o = 128; o; o >>= 1) {
        if (tid < o) { ss[tid] += ss[tid + o]; sc[tid] += sc[tid + o]; }
        __syncthreads();
    }
    if (tid == 0) out[0] = (sc[0] > 0.0f) ? (ss[0] / sc[0]) : 0.0f;
}

// ---------------------------------------------------------------------------
extern "C" void kernel_launch(void* const* d_in, const int* in_sizes, int n_in,
                              void* d_out, int out_size) {
    const float* emb = (const float*)d_in[0];
    const int*   cat = (const int*)d_in[1];   // int64 in reference, int32 on the wire
    // d_in[2] = font_labels, unused

    cudaFuncSetAttribute(k_mma, cudaFuncAttributeMaxDynamicSharedMemorySize, SMEM_BYTES);

    k_normalize<<<BDIM, 64>>>(emb);

    dim3 grid(BDIM / BM, NJC);                // 64 x 8
    k_mma<<<grid, 256, SMEM_BYTES>>>(cat);

    k_final<<<1, 256>>>((float*)d_out);
}

// round 5
// speedup vs baseline: 7.1398x; 1.8347x over previous
#include <cuda_runtime.h>
#include <cuda_fp16.h>
#include <cstdint>

// B=8192, D=256, categories int32 on the wire.
#define BDIM 8192
#define DDIM 256
#define INV_T 1.4285714285714286f
#define M0    1.4285714285714286f

#define BM 128
#define BN 128
#define NJC 2                        // j-chunks (blockIdx.y)
#define NT  (BDIM / NJC / BN)        // 32 j-tiles per CTA
#define THREADS 256                  // 8 warps: 4 in M x 2 in N

#define STRIDE 528                   // bytes per tile row (256 fp16 = 512B + 16B pad)
#define TILEB  (128 * STRIDE)        // 67584 B per tile buffer
#define A_OFF   0
#define B_OFF   TILEB                // two B buffers follow A
#define CAT_OFF (3 * TILEB)          // int[2][128]
#define RED_OFF (CAT_OFF + 1024)     // float[128][8]
#define SMEM_NEED (RED_OFF + 4096 + 16)

__device__ __half g_normh[BDIM * DDIM];   // fp16 normalized embeddings (4 MB)
__device__ float  g_pos [NJC * BDIM];
__device__ float  g_negs[NJC * BDIM];

// ---------------- helpers ----------------
__device__ __forceinline__ uint32_t smem_u32(const void* p) {
    uint32_t a;
    asm("{ .reg .u64 t; cvta.to.shared.u64 t, %1; cvt.u32.u64 %0, t; }" : "=r"(a) : "l"(p));
    return a;
}
__device__ __forceinline__ void cp16(uint32_t dst, const void* src) {
    asm volatile("cp.async.cg.shared.global [%0], [%1], 16;" :: "r"(dst), "l"(src));
}
__device__ __forceinline__ void cp_commit() {
    asm volatile("cp.async.commit_group;" ::: "memory");
}
__device__ __forceinline__ void cp_wait0() {
    asm volatile("cp.async.wait_group 0;" ::: "memory");
}
__device__ __forceinline__ void ldm4(uint32_t r[4], uint32_t addr) {
    asm volatile("ldmatrix.sync.aligned.m8n8.x4.shared.b16 {%0,%1,%2,%3}, [%4];"
                 : "=r"(r[0]), "=r"(r[1]), "=r"(r[2]), "=r"(r[3]) : "r"(addr));
}
__device__ __forceinline__ void mma16816(float d[4], const uint32_t a[4],
                                         uint32_t b0, uint32_t b1) {
    asm volatile(
        "mma.sync.aligned.m16n8k16.row.col.f32.f16.f16.f32 "
        "{%0,%1,%2,%3},{%4,%5,%6,%7},{%8,%9},{%0,%1,%2,%3};\n"
        : "+f"(d[0]), "+f"(d[1]), "+f"(d[2]), "+f"(d[3])
        : "r"(a[0]), "r"(a[1]), "r"(a[2]), "r"(a[3]), "r"(b0), "r"(b1));
}
// async-copy one 128x256 fp16 tile (row-major, k contiguous) into padded smem
__device__ __forceinline__ void tile_cp(uint32_t dstBase, const uint4* src, int rowStart) {
    int tid = threadIdx.x;
    #pragma unroll
    for (int t = 0; t < 16; t++) {
        int idx = tid + t * THREADS;       // 0..4095 16B chunks
        int r   = idx >> 5;                // 32 chunks per row
        int c   = idx & 31;
        cp16(dstBase + r * STRIDE + c * 16, src + (size_t)(rowStart + r) * 32 + c);
    }
}

// ---------------------------------------------------------------------------
// Kernel 1: row L2-normalize, output fp16.
// ---------------------------------------------------------------------------
__global__ void k_normalize(const float* __restrict__ emb) {
    int row = blockIdx.x;
    int t = threadIdx.x;                   // 0..63
    float4 v = ((const float4*)(emb + (size_t)row * DDIM))[t];
    float ss = v.x * v.x + v.y * v.y + v.z * v.z + v.w * v.w;
    #pragma unroll
    for (int o = 16; o; o >>= 1) ss += __shfl_xor_sync(0xFFFFFFFFu, ss, o);
    __shared__ float sw2[2];
    if ((t & 31) == 0) sw2[t >> 5] = ss;
    __syncthreads();
    float inv = 1.0f / fmaxf(sqrtf(sw2[0] + sw2[1]), 1e-12f);
    __half2 p0 = __floats2half2_rn(v.x * inv, v.y * inv);
    __half2 p1 = __floats2half2_rn(v.z * inv, v.w * inv);
    uint2 o;
    o.x = *reinterpret_cast<uint32_t*>(&p0);
    o.y = *reinterpret_cast<uint32_t*>(&p1);
    ((uint2*)(g_normh + (size_t)row * DDIM))[t] = o;
}

// ---------------------------------------------------------------------------
// Kernel 2: fp16 mma.sync sims GEMM fused with masked max / sum-exp epilogue.
// A tile resident; B full tiles double-buffered via cp.async; ldmatrix frags.
// ---------------------------------------------------------------------------
__global__ void __launch_bounds__(THREADS, 1)
k_mma(const int* __restrict__ cat) {
    extern __shared__ char smRaw[];
    char* smBase = (char*)((((uintptr_t)smRaw) + 15) & ~(uintptr_t)15);
    const uint32_t base  = smem_u32(smBase);
    const uint32_t aAddr = base + A_OFF;
    const uint32_t bAddr = base + B_OFF;
    int*   sCat = (int*)(smBase + CAT_OFF);
    float* sRed = (float*)(smBase + RED_OFF);

    const int tid  = threadIdx.x;
    const int lane = tid & 31;
    const int warp = tid >> 5;
    const int wm = warp & 3;               // 32-row group
    const int wn = warp >> 2;              // 64-col group
    const int g  = lane >> 3;              // ldmatrix address group
    const int r7 = lane & 7;
    const int l4 = lane >> 2;
    const int lm = lane & 3;
    const int rowBase = blockIdx.x * BM;
    const int jBase   = blockIdx.y * (NT * BN);

    // per-lane ldmatrix base addresses
    uint32_t aPtr[2], bOff[4];
    #pragma unroll
    for (int mf = 0; mf < 2; mf++)
        aPtr[mf] = aAddr + (uint32_t)(wm * 32 + mf * 16 + (g & 1) * 8 + r7) * STRIDE
                         + (uint32_t)(g >> 1) * 16;
    #pragma unroll
    for (int np = 0; np < 4; np++)
        bOff[np] = (uint32_t)(wn * 64 + np * 16 + (g >> 1) * 8 + r7) * STRIDE
                 + (uint32_t)(g & 1) * 16;

    const uint4* src = (const uint4*)g_normh;

    // prologue: A tile + B tile 0 + cats 0
    tile_cp(aAddr, src, rowBase);
    tile_cp(bAddr, src, jBase);
    cp_commit();
    if (tid < BM) sCat[tid] = cat[jBase + tid];
    cp_wait0();
    __syncthreads();

    // per-thread row categories + running reductions
    int   ci  [2][2];
    float posm[2][2], negs[2][2];
    #pragma unroll
    for (int mf = 0; mf < 2; mf++)
        #pragma unroll
        for (int h = 0; h < 2; h++) {
            ci[mf][h]   = cat[rowBase + wm * 32 + mf * 16 + h * 8 + l4];
            posm[mf][h] = -1e30f;
            negs[mf][h] = 0.0f;
        }

    for (int jj = 0; jj < NT; jj++) {
        const int cur = jj & 1, nb = cur ^ 1;
        if (jj + 1 < NT) {
            tile_cp(bAddr + nb * TILEB, src, jBase + (jj + 1) * BN);
            cp_commit();
            if (tid < BM) sCat[nb * BM + tid] = cat[jBase + (jj + 1) * BN + tid];
        }

        float acc[2][8][4];
        #pragma unroll
        for (int mf = 0; mf < 2; mf++)
            #pragma unroll
            for (int nf = 0; nf < 8; nf++)
                #pragma unroll
                for (int c = 0; c < 4; c++) acc[mf][nf][c] = 0.0f;

        const uint32_t bBuf = bAddr + cur * TILEB;
        #pragma unroll
        for (int kc = 0; kc < 16; kc++) {
            uint32_t af[2][4], bf[4][4];
            ldm4(af[0], aPtr[0] + kc * 32);
            ldm4(af[1], aPtr[1] + kc * 32);
            #pragma unroll
            for (int np = 0; np < 4; np++) ldm4(bf[np], bBuf + bOff[np] + kc * 32);
            #pragma unroll
            for (int mf = 0; mf < 2; mf++)
                #pragma unroll
                for (int nf = 0; nf < 8; nf++)
                    mma16816(acc[mf][nf], af[mf],
                             bf[nf >> 1][(nf & 1) * 2], bf[nf >> 1][(nf & 1) * 2 + 1]);
        }

        // fused epilogue: masked hardest-positive max + sum exp(sim - M0)
        const int jt = jBase + jj * BN;
        const int* catT = sCat + cur * BM;
        #pragma unroll
        for (int nf = 0; nf < 8; nf++) {
            int col0 = wn * 64 + nf * 8 + lm * 2;
            int cj0 = catT[col0], cj1 = catT[col0 + 1];
            int jg0 = jt + col0;
            #pragma unroll
            for (int mf = 0; mf < 2; mf++) {
                #pragma unroll
                for (int h = 0; h < 2; h++) {
                    int rg = rowBase + wm * 32 + mf * 16 + h * 8 + l4;
                    int cir = ci[mf][h];
                    float s0 = acc[mf][nf][2 * h + 0] * INV_T;
                    float s1 = acc[mf][nf][2 * h + 1] * INV_T;
                    float e0 = __expf(s0 - M0);
                    float e1 = __expf(s1 - M0);
                    if (cir != cj0)          negs[mf][h] += e0;
                    else if (jg0 != rg)      posm[mf][h] = fmaxf(posm[mf][h], s0);
                    if (cir != cj1)          negs[mf][h] += e1;
                    else if (jg0 + 1 != rg)  posm[mf][h] = fmaxf(posm[mf][h], s1);
                }
            }
        }

        if (jj + 1 < NT) { cp_wait0(); }
        __syncthreads();                  // B[nb]+cats ready; epilogue done before overwrite
    }

    // cross-thread reduction: 8 contributors per row (wn x lm)
    #pragma unroll
    for (int mf = 0; mf < 2; mf++)
        #pragma unroll
        for (int h = 0; h < 2; h++)
            sRed[(wm * 32 + mf * 16 + h * 8 + l4) * 8 + wn * 4 + lm] = posm[mf][h];
    __syncthreads();
    if (tid < BM) {
        float p = -1e30f;
        #pragma unroll
        for (int x = 0; x < 8; x++) p = fmaxf(p, sRed[tid * 8 + x]);
        g_pos[blockIdx.y * BDIM + rowBase + tid] = p;
    }
    __syncthreads();
    #pragma unroll
    for (int mf = 0; mf < 2; mf++)
        #pragma unroll
        for (int h = 0; h < 2; h++)
            sRed[(wm * 32 + mf * 16 + h * 8 + l4) * 8 + wn * 4 + lm] = negs[mf][h];
    __syncthreads();
    if (tid < BM) {
        float s = 0.0f;
        #pragma unroll
        for (int x = 0; x < 8; x++) s += sRed[tid * 8 + x];
        g_negs[blockIdx.y * BDIM + rowBase + tid] = s;
    }
}

// ---------------------------------------------------------------------------
// Kernel 3: deterministic merge over j-chunks + per-row loss + mean.
// ---------------------------------------------------------------------------
__global__ void k_final(float* __restrict__ out) {
    int tid = threadIdx.x;
    float sum = 0.0f, cnt = 0.0f;
    for (int r = tid; r < BDIM; r += 256) {
        float p = -1e30f, ns = 0.0f;
        #pragma unroll
        for (int c = 0; c < NJC; c++) {
            p = fmaxf(p, g_pos[c * BDIM + r]);
            ns += g_negs[c * BDIM + r];
        }
        bool valid = (p > -1e29f) && (ns > 0.0f);
        if (valid) {
            float lse = M0 + logf(expf(p - M0) + ns);
            sum += (lse - p);
            cnt += 1.0f;
        }
    }
    __shared__ float ss[256], sc[256];
    ss[tid] = sum; sc[tid] = cnt;
    __syncthreads();
    for (int o = 128; o; o >>= 1) {
        if (tid < o) { ss[tid] += ss[tid + o]; sc[tid] += sc[tid + o]; }
        __syncthreads();
    }
    if (tid == 0) out[0] = (sc[0] > 0.0f) ? (ss[0] / sc[0]) : 0.0f;
}

// ---------------------------------------------------------------------------
extern "C" void kernel_launch(void* const* d_in, const int* in_sizes, int n_in,
                              void* d_out, int out_size) {
    const float* emb = (const float*)d_in[0];
    const int*   cat = (const int*)d_in[1];
    // d_in[2] = font_labels, unused

    cudaFuncSetAttribute(k_mma, cudaFuncAttributeMaxDynamicSharedMemorySize, SMEM_NEED);

    k_normalize<<<BDIM, 64>>>(emb);

    dim3 grid(BDIM / BM, NJC);            // 64 x 2 = 128 CTAs (one wave)
    k_mma<<<grid, THREADS, SMEM_NEED>>>(cat);

    k_final<<<1, 256>>>((float*)d_out);
}

// round 6
// speedup vs baseline: 8.3137x; 1.1644x over previous
#include <cuda_runtime.h>
#include <cuda_fp16.h>
#include <cstdint>

// B=8192, D=256, categories int32 on the wire.
#define BDIM 8192
#define DDIM 256
#define INV_T 1.4285714285714286f
#define M0    1.4285714285714286f

#define BM 128
#define BN 128
#define NJC 2                        // j-chunks (blockIdx.y)
#define NT  (BDIM / NJC / BN)        // 32 j-tiles per CTA
#define THREADS 512                  // 16 warps: 4 in M x 4 in N

#define STRIDE 528                   // bytes per tile row (256 fp16 = 512B + 16B pad)
#define TILEB  (128 * STRIDE)        // 67584 B per tile buffer
#define A_OFF   0
#define B_OFF   TILEB                // two B buffers follow A
#define CAT_OFF (3 * TILEB)          // int[2][128]
#define RED_OFF (CAT_OFF + 1024)     // float[128][16]
#define SMEM_NEED (RED_OFF + 8192 + 16)

__device__ __half g_normh[BDIM * DDIM];   // fp16 normalized embeddings (4 MB)
__device__ float  g_pos [NJC * BDIM];
__device__ float  g_negs[NJC * BDIM];

// ---------------- helpers ----------------
__device__ __forceinline__ uint32_t smem_u32(const void* p) {
    uint32_t a;
    asm("{ .reg .u64 t; cvta.to.shared.u64 t, %1; cvt.u32.u64 %0, t; }" : "=r"(a) : "l"(p));
    return a;
}
__device__ __forceinline__ void cp16(uint32_t dst, const void* src) {
    asm volatile("cp.async.cg.shared.global [%0], [%1], 16;" :: "r"(dst), "l"(src));
}
__device__ __forceinline__ void cp_commit() {
    asm volatile("cp.async.commit_group;" ::: "memory");
}
__device__ __forceinline__ void cp_wait0() {
    asm volatile("cp.async.wait_group 0;" ::: "memory");
}
__device__ __forceinline__ void ldm4(uint32_t r[4], uint32_t addr) {
    asm volatile("ldmatrix.sync.aligned.m8n8.x4.shared.b16 {%0,%1,%2,%3}, [%4];"
                 : "=r"(r[0]), "=r"(r[1]), "=r"(r[2]), "=r"(r[3]) : "r"(addr));
}
__device__ __forceinline__ void mma16816(float d[4], const uint32_t a[4],
                                         uint32_t b0, uint32_t b1) {
    asm volatile(
        "mma.sync.aligned.m16n8k16.row.col.f32.f16.f16.f32 "
        "{%0,%1,%2,%3},{%4,%5,%6,%7},{%8,%9},{%0,%1,%2,%3};\n"
        : "+f"(d[0]), "+f"(d[1]), "+f"(d[2]), "+f"(d[3])
        : "r"(a[0]), "r"(a[1]), "r"(a[2]), "r"(a[3]), "r"(b0), "r"(b1));
}
// async-copy one 128x256 fp16 tile (row-major, k contiguous) into padded smem
__device__ __forceinline__ void tile_cp(uint32_t dstBase, const uint4* src, int rowStart) {
    int tid = threadIdx.x;
    #pragma unroll
    for (int t = 0; t < 8; t++) {
        int idx = tid + t * THREADS;       // 0..4095 16B chunks
        int r   = idx >> 5;                // 32 chunks per row
        int c   = idx & 31;
        cp16(dstBase + r * STRIDE + c * 16, src + (size_t)(rowStart + r) * 32 + c);
    }
}

// ---------------------------------------------------------------------------
// Kernel 1: row L2-normalize, output fp16.
// ---------------------------------------------------------------------------
__global__ void k_normalize(const float* __restrict__ emb) {
    int row = blockIdx.x;
    int t = threadIdx.x;                   // 0..63
    float4 v = ((const float4*)(emb + (size_t)row * DDIM))[t];
    float ss = v.x * v.x + v.y * v.y + v.z * v.z + v.w * v.w;
    #pragma unroll
    for (int o = 16; o; o >>= 1) ss += __shfl_xor_sync(0xFFFFFFFFu, ss, o);
    __shared__ float sw2[2];
    if ((t & 31) == 0) sw2[t >> 5] = ss;
    __syncthreads();
    float inv = 1.0f / fmaxf(sqrtf(sw2[0] + sw2[1]), 1e-12f);
    __half2 p0 = __floats2half2_rn(v.x * inv, v.y * inv);
    __half2 p1 = __floats2half2_rn(v.z * inv, v.w * inv);
    uint2 o;
    o.x = *reinterpret_cast<uint32_t*>(&p0);
    o.y = *reinterpret_cast<uint32_t*>(&p1);
    ((uint2*)(g_normh + (size_t)row * DDIM))[t] = o;
}

// ---------------------------------------------------------------------------
// Kernel 2: fp16 mma.sync sims GEMM fused with masked max / sum-exp epilogue.
// 16 warps (4Mx4N, 32x32 per warp). A tile resident; B double-buffered cp.async.
// ---------------------------------------------------------------------------
__global__ void __launch_bounds__(THREADS, 1)
k_mma(const int* __restrict__ cat) {
    extern __shared__ char smRaw[];
    char* smBase = (char*)((((uintptr_t)smRaw) + 15) & ~(uintptr_t)15);
    const uint32_t base  = smem_u32(smBase);
    const uint32_t aAddr = base + A_OFF;
    const uint32_t bAddr = base + B_OFF;
    int*   sCat = (int*)(smBase + CAT_OFF);
    float* sRed = (float*)(smBase + RED_OFF);

    const int tid  = threadIdx.x;
    const int lane = tid & 31;
    const int warp = tid >> 5;
    const int wm = warp & 3;               // 32-row group
    const int wn = warp >> 2;              // 32-col group
    const int g  = lane >> 3;              // ldmatrix address group
    const int r7 = lane & 7;
    const int l4 = lane >> 2;
    const int lm = lane & 3;
    const int rowBase = blockIdx.x * BM;
    const int jBase   = blockIdx.y * (NT * BN);

    // per-lane ldmatrix base addresses
    uint32_t aPtr[2], bOff[2];
    #pragma unroll
    for (int mf = 0; mf < 2; mf++)
        aPtr[mf] = aAddr + (uint32_t)(wm * 32 + mf * 16 + (g & 1) * 8 + r7) * STRIDE
                         + (uint32_t)(g >> 1) * 16;
    #pragma unroll
    for (int np = 0; np < 2; np++)
        bOff[np] = (uint32_t)(wn * 32 + np * 16 + (g >> 1) * 8 + r7) * STRIDE
                 + (uint32_t)(g & 1) * 16;

    const uint4* src = (const uint4*)g_normh;

    // prologue: A tile + B tile 0 + cats 0
    tile_cp(aAddr, src, rowBase);
    tile_cp(bAddr, src, jBase);
    cp_commit();
    if (tid < BM) sCat[tid] = cat[jBase + tid];
    cp_wait0();
    __syncthreads();

    // per-thread row categories + running reductions
    int   ci  [2][2];
    float posm[2][2], negs[2][2];
    #pragma unroll
    for (int mf = 0; mf < 2; mf++)
        #pragma unroll
        for (int h = 0; h < 2; h++) {
            ci[mf][h]   = cat[rowBase + wm * 32 + mf * 16 + h * 8 + l4];
            posm[mf][h] = -1e30f;
            negs[mf][h] = 0.0f;
        }

    for (int jj = 0; jj < NT; jj++) {
        const int cur = jj & 1, nb = cur ^ 1;
        if (jj + 1 < NT) {
            tile_cp(bAddr + nb * TILEB, src, jBase + (jj + 1) * BN);
            cp_commit();
            if (tid < BM) sCat[nb * BM + tid] = cat[jBase + (jj + 1) * BN + tid];
        }

        float acc[2][4][4];
        #pragma unroll
        for (int mf = 0; mf < 2; mf++)
            #pragma unroll
            for (int nf = 0; nf < 4; nf++)
                #pragma unroll
                for (int c = 0; c < 4; c++) acc[mf][nf][c] = 0.0f;

        const uint32_t bBuf = bAddr + cur * TILEB;
        #pragma unroll
        for (int kc = 0; kc < 16; kc++) {
            uint32_t af[2][4], bf[2][4];
            ldm4(af[0], aPtr[0] + kc * 32);
            ldm4(af[1], aPtr[1] + kc * 32);
            ldm4(bf[0], bBuf + bOff[0] + kc * 32);
            ldm4(bf[1], bBuf + bOff[1] + kc * 32);
            #pragma unroll
            for (int mf = 0; mf < 2; mf++)
                #pragma unroll
                for (int nf = 0; nf < 4; nf++)
                    mma16816(acc[mf][nf], af[mf],
                             bf[nf >> 1][(nf & 1) * 2], bf[nf >> 1][(nf & 1) * 2 + 1]);
        }

        // fused epilogue: masked hardest-positive max + sum exp(sim - M0)
        const int jt = jBase + jj * BN;
        const int* catT = sCat + cur * BM;
        #pragma unroll
        for (int nf = 0; nf < 4; nf++) {
            int col0 = wn * 32 + nf * 8 + lm * 2;
            int cj0 = catT[col0], cj1 = catT[col0 + 1];
            int jg0 = jt + col0;
            #pragma unroll
            for (int mf = 0; mf < 2; mf++) {
                #pragma unroll
                for (int h = 0; h < 2; h++) {
                    int rg = rowBase + wm * 32 + mf * 16 + h * 8 + l4;
                    int cir = ci[mf][h];
                    float s0 = acc[mf][nf][2 * h + 0] * INV_T;
                    float s1 = acc[mf][nf][2 * h + 1] * INV_T;
                    float e0 = __expf(s0 - M0);
                    float e1 = __expf(s1 - M0);
                    if (cir != cj0)          negs[mf][h] += e0;
                    else if (jg0 != rg)      posm[mf][h] = fmaxf(posm[mf][h], s0);
                    if (cir != cj1)          negs[mf][h] += e1;
                    else if (jg0 + 1 != rg)  posm[mf][h] = fmaxf(posm[mf][h], s1);
                }
            }
        }

        if (jj + 1 < NT) { cp_wait0(); }
        __syncthreads();                  // B[nb]+cats ready; epilogue done before overwrite
    }

    // cross-thread reduction: 16 contributors per row (wn x lm)
    #pragma unroll
    for (int mf = 0; mf < 2; mf++)
        #pragma unroll
        for (int h = 0; h < 2; h++)
            sRed[(wm * 32 + mf * 16 + h * 8 + l4) * 16 + wn * 4 + lm] = posm[mf][h];
    __syncthreads();
    if (tid < BM) {
        float p = -1e30f;
        #pragma unroll
        for (int x = 0; x < 16; x++) p = fmaxf(p, sRed[tid * 16 + x]);
        g_pos[blockIdx.y * BDIM + rowBase + tid] = p;
    }
    __syncthreads();
    #pragma unroll
    for (int mf = 0; mf < 2; mf++)
        #pragma unroll
        for (int h = 0; h < 2; h++)
            sRed[(wm * 32 + mf * 16 + h * 8 + l4) * 16 + wn * 4 + lm] = negs[mf][h];
    __syncthreads();
    if (tid < BM) {
        float s = 0.0f;
        #pragma unroll
        for (int x = 0; x < 16; x++) s += sRed[tid * 16 + x];
        g_negs[blockIdx.y * BDIM + rowBase + tid] = s;
    }
}

// ---------------------------------------------------------------------------
// Kernel 3: deterministic merge over j-chunks + per-row loss + mean.
// ---------------------------------------------------------------------------
__global__ void k_final(float* __restrict__ out) {
    int tid = threadIdx.x;
    float sum = 0.0f, cnt = 0.0f;
    for (int r = tid; r < BDIM; r += 256) {
        float p = -1e30f, ns = 0.0f;
        #pragma unroll
        for (int c = 0; c < NJC; c++) {
            p = fmaxf(p, g_pos[c * BDIM + r]);
            ns += g_negs[c * BDIM + r];
        }
        bool valid = (p > -1e29f) && (ns > 0.0f);
        if (valid) {
            float lse = M0 + logf(expf(p - M0) + ns);
            sum += (lse - p);
            cnt += 1.0f;
        }
    }
    __shared__ float ss[256], sc[256];
    ss[tid] = sum; sc[tid] = cnt;
    __syncthreads();
    for (int o = 128; o; o >>= 1) {
        if (tid < o) { ss[tid] += ss[tid + o]; sc[tid] += sc[tid + o]; }
        __syncthreads();
    }
    if (tid == 0) out[0] = (sc[0] > 0.0f) ? (ss[0] / sc[0]) : 0.0f;
}

// ---------------------------------------------------------------------------
extern "C" void kernel_launch(void* const* d_in, const int* in_sizes, int n_in,
                              void* d_out, int out_size) {
    const float* emb = (const float*)d_in[0];
    const int*   cat = (const int*)d_in[1];
    // d_in[2] = font_labels, unused

    cudaFuncSetAttribute(k_mma, cudaFuncAttributeMaxDynamicSharedMemorySize, SMEM_NEED);

    k_normalize<<<BDIM, 64>>>(emb);

    dim3 grid(BDIM / BM, NJC);            // 64 x 2 = 128 CTAs (one wave)
    k_mma<<<grid, THREADS, SMEM_NEED>>>(cat);

    k_final<<<1, 256>>>((float*)d_out);
}

// round 7
// speedup vs baseline: 13.9104x; 1.6732x over previous
#include <cuda_runtime.h>
#include <cuda_fp16.h>
#include <cstdint>

// B=8192, D=256, categories int32 on the wire.
#define BDIM 8192
#define DDIM 256
#define INV_T 1.4285714285714286f
#define M0    1.4285714285714286f

#define BM 128
#define NBLK 64                      // 8192 / 128 row blocks
#define THREADS 512                  // 16 warps: 4 in M x 4 in N

#define STRIDE 528                   // bytes per tile row (256 fp16 = 512B + 16B pad)
#define TILEB  (128 * STRIDE)
#define A_OFF   0
#define B_OFF   TILEB                // two B buffers follow A
#define CAT_OFF (3 * TILEB)          // int[2][128]
#define RED_OFF (CAT_OFF + 1024)     // shared reduction buffer (8KB)
#define SMEM_NEED (RED_OFF + 8192 + 16)

#define SLOTS (NBLK * BDIM)          // 524288 scratch entries per array

__device__ __half g_normh[BDIM * DDIM];
__device__ float  g_pos [SLOTS];     // P[c][r]: contributor col-block c, row r
__device__ float  g_negs[SLOTS];
__device__ float  g_psum[NBLK];
__device__ float  g_pcnt[NBLK];

// ---------------- helpers ----------------
__device__ __forceinline__ uint32_t smem_u32(const void* p) {
    uint32_t a;
    asm("{ .reg .u64 t; cvta.to.shared.u64 t, %1; cvt.u32.u64 %0, t; }" : "=r"(a) : "l"(p));
    return a;
}
__device__ __forceinline__ void cp16(uint32_t dst, const void* src) {
    asm volatile("cp.async.cg.shared.global [%0], [%1], 16;" :: "r"(dst), "l"(src));
}
__device__ __forceinline__ void cp_commit() {
    asm volatile("cp.async.commit_group;" ::: "memory");
}
__device__ __forceinline__ void cp_wait0() {
    asm volatile("cp.async.wait_group 0;" ::: "memory");
}
__device__ __forceinline__ void ldm4(uint32_t r[4], uint32_t addr) {
    asm volatile("ldmatrix.sync.aligned.m8n8.x4.shared.b16 {%0,%1,%2,%3}, [%4];"
                 : "=r"(r[0]), "=r"(r[1]), "=r"(r[2]), "=r"(r[3]) : "r"(addr));
}
__device__ __forceinline__ void mma16816(float d[4], const uint32_t a[4],
                                         uint32_t b0, uint32_t b1) {
    asm volatile(
        "mma.sync.aligned.m16n8k16.row.col.f32.f16.f16.f32 "
        "{%0,%1,%2,%3},{%4,%5,%6,%7},{%8,%9},{%0,%1,%2,%3};\n"
        : "+f"(d[0]), "+f"(d[1]), "+f"(d[2]), "+f"(d[3])
        : "r"(a[0]), "r"(a[1]), "r"(a[2]), "r"(a[3]), "r"(b0), "r"(b1));
}
__device__ __forceinline__ void tile_cp(uint32_t dstBase, const uint4* src, int rowStart) {
    int tid = threadIdx.x;
    #pragma unroll
    for (int t = 0; t < 8; t++) {
        int idx = tid + t * THREADS;       // 0..4095 16B chunks
        int r   = idx >> 5;
        int c   = idx & 31;
        cp16(dstBase + r * STRIDE + c * 16, src + (size_t)(rowStart + r) * 32 + c);
    }
}
// write accumulated row stats for segment (row block curIt) into slot column segC
__device__ __forceinline__ void flush_rows(float* sRed, float posm[2][2], float negs[2][2],
                                           int wm, int wn, int l4, int lm, int tid,
                                           int curIt, int segC) {
    #pragma unroll
    for (int mf = 0; mf < 2; mf++)
        #pragma unroll
        for (int h = 0; h < 2; h++)
            sRed[(wm * 32 + mf * 16 + h * 8 + l4) * 16 + wn * 4 + lm] = posm[mf][h];
    __syncthreads();
    if (tid < BM) {
        float p = -1e30f;
        #pragma unroll
        for (int x = 0; x < 16; x++) p = fmaxf(p, sRed[tid * 16 + x]);
        g_pos[segC * BDIM + curIt * BM + tid] = p;
    }
    __syncthreads();
    #pragma unroll
    for (int mf = 0; mf < 2; mf++)
        #pragma unroll
        for (int h = 0; h < 2; h++)
            sRed[(wm * 32 + mf * 16 + h * 8 + l4) * 16 + wn * 4 + lm] = negs[mf][h];
    __syncthreads();
    if (tid < BM) {
        float s = 0.0f;
        #pragma unroll
        for (int x = 0; x < 16; x++) s += sRed[tid * 16 + x];
        g_negs[segC * BDIM + curIt * BM + tid] = s;
    }
    __syncthreads();
}

// ---------------------------------------------------------------------------
// Kernel 0: scratch identity init.
// ---------------------------------------------------------------------------
__global__ void k_init() {
    int i = blockIdx.x * 512 + threadIdx.x;   // grid = SLOTS/512
    g_pos[i]  = -1e30f;
    g_negs[i] = 0.0f;
}

// ---------------------------------------------------------------------------
// Kernel 1: row L2-normalize, output fp16.
// ---------------------------------------------------------------------------
__global__ void k_normalize(const float* __restrict__ emb) {
    int row = blockIdx.x;
    int t = threadIdx.x;                   // 0..63
    float4 v = ((const float4*)(emb + (size_t)row * DDIM))[t];
    float ss = v.x * v.x + v.y * v.y + v.z * v.z + v.w * v.w;
    #pragma unroll
    for (int o = 16; o; o >>= 1) ss += __shfl_xor_sync(0xFFFFFFFFu, ss, o);
    __shared__ float sw2[2];
    if ((t & 31) == 0) sw2[t >> 5] = ss;
    __syncthreads();
    float inv = 1.0f / fmaxf(sqrtf(sw2[0] + sw2[1]), 1e-12f);
    __half2 p0 = __floats2half2_rn(v.x * inv, v.y * inv);
    __half2 p1 = __floats2half2_rn(v.z * inv, v.w * inv);
    uint2 o;
    o.x = *reinterpret_cast<uint32_t*>(&p0);
    o.y = *reinterpret_cast<uint32_t*>(&p1);
    ((uint2*)(g_normh + (size_t)row * DDIM))[t] = o;
}

// ---------------------------------------------------------------------------
// Kernel 2: upper-triangle fp16 mma.sync sims GEMM; each off-diag tile feeds
// BOTH row-side (i rows) and col-side (j rows, via symmetry) masked stats.
// Pair p handles row-blocks {p, 63-p} (65 tiles), split into 4 chunk-CTAs.
// ---------------------------------------------------------------------------
__global__ void __launch_bounds__(THREADS, 1)
k_mma(const int* __restrict__ cat) {
    extern __shared__ char smRaw[];
    char* smBase = (char*)((((uintptr_t)smRaw) + 15) & ~(uintptr_t)15);
    const uint32_t base  = smem_u32(smBase);
    const uint32_t aAddr = base + A_OFF;
    const uint32_t bAddr = base + B_OFF;
    int*   sCat = (int*)(smBase + CAT_OFF);
    float* sRed = (float*)(smBase + RED_OFF);

    const int tid  = threadIdx.x;
    const int lane = tid & 31;
    const int warp = tid >> 5;
    const int wm = warp & 3;
    const int wn = warp >> 2;
    const int g  = lane >> 3;
    const int r7 = lane & 7;
    const int l4 = lane >> 2;
    const int lm = lane & 3;

    // tile schedule
    const int p     = blockIdx.x >> 2;
    const int chunk = blockIdx.x & 3;
    const int it1 = p, n1 = NBLK - p, it2 = NBLK - 1 - p;
    const int start = (chunk == 0) ? 0 : 17 + (chunk - 1) * 16;
    const int count = (chunk == 0) ? 17 : 16;
    const int end   = start + count;

    #define TILE_OF(k, it, jt) do { \
        if ((k) < n1) { it = it1; jt = p + (k); } \
        else          { it = it2; jt = (NBLK - 1 - p) + ((k) - n1); } \
    } while (0)

    // per-lane ldmatrix base addresses
    uint32_t aPtr[2], bOff[2];
    #pragma unroll
    for (int mf = 0; mf < 2; mf++)
        aPtr[mf] = aAddr + (uint32_t)(wm * 32 + mf * 16 + (g & 1) * 8 + r7) * STRIDE
                         + (uint32_t)(g >> 1) * 16;
    #pragma unroll
    for (int np = 0; np < 2; np++)
        bOff[np] = (uint32_t)(wn * 32 + np * 16 + (g >> 1) * 8 + r7) * STRIDE
                 + (uint32_t)(g & 1) * 16;

    const uint4* src = (const uint4*)g_normh;

    // prologue
    int it0, jt0; TILE_OF(start, it0, jt0);
    tile_cp(aAddr, src, it0 * BM);
    tile_cp(bAddr, src, jt0 * BM);
    cp_commit();
    if (tid < BM) sCat[tid] = cat[jt0 * BM + tid];
    cp_wait0();
    __syncthreads();

    int curIt = it0, segC = jt0;
    int   ci[2][2];
    float posm[2][2], negs[2][2];
    #pragma unroll
    for (int mf = 0; mf < 2; mf++)
        #pragma unroll
        for (int h = 0; h < 2; h++) {
            ci[mf][h]   = cat[curIt * BM + wm * 32 + mf * 16 + h * 8 + l4];
            posm[mf][h] = -1e30f;
            negs[mf][h] = 0.0f;
        }

    for (int kk = start; kk < end; kk++) {
        int it, jt; TILE_OF(kk, it, jt);
        const int cur = (kk - start) & 1;

        if (it != curIt) {   // segment change: flush, reload A + row cats
            flush_rows(sRed, posm, negs, wm, wn, l4, lm, tid, curIt, segC);
            tile_cp(aAddr, src, it * BM);
            cp_commit();
            cp_wait0();
            __syncthreads();
            curIt = it; segC = jt;
            #pragma unroll
            for (int mf = 0; mf < 2; mf++)
                #pragma unroll
                for (int h = 0; h < 2; h++) {
                    ci[mf][h]   = cat[curIt * BM + wm * 32 + mf * 16 + h * 8 + l4];
                    posm[mf][h] = -1e30f;
                    negs[mf][h] = 0.0f;
                }
        }

        if (kk + 1 < end) {  // prefetch next B + its cats
            int itn, jtn; TILE_OF(kk + 1, itn, jtn);
            tile_cp(bAddr + (cur ^ 1) * TILEB, src, jtn * BM);
            cp_commit();
            if (tid < BM) sCat[(cur ^ 1) * BM + tid] = cat[jtn * BM + tid];
        }

        float acc[2][4][4];
        #pragma unroll
        for (int mf = 0; mf < 2; mf++)
            #pragma unroll
            for (int nf = 0; nf < 4; nf++)
                #pragma unroll
                for (int c = 0; c < 4; c++) acc[mf][nf][c] = 0.0f;

        const uint32_t bBuf = bAddr + cur * TILEB;
        #pragma unroll
        for (int kc = 0; kc < 16; kc++) {
            uint32_t af[2][4], bf[2][4];
            ldm4(af[0], aPtr[0] + kc * 32);
            ldm4(af[1], aPtr[1] + kc * 32);
            ldm4(bf[0], bBuf + bOff[0] + kc * 32);
            ldm4(bf[1], bBuf + bOff[1] + kc * 32);
            #pragma unroll
            for (int mf = 0; mf < 2; mf++)
                #pragma unroll
                for (int nf = 0; nf < 4; nf++)
                    mma16816(acc[mf][nf], af[mf],
                             bf[nf >> 1][(nf & 1) * 2], bf[nf >> 1][(nf & 1) * 2 + 1]);
        }

        // ---- fused dual-sided epilogue ----
        const bool diag = (it == jt);
        float cPos[4][2], cNeg[4][2];
        #pragma unroll
        for (int nf = 0; nf < 4; nf++) {
            cPos[nf][0] = cPos[nf][1] = -1e30f;
            cNeg[nf][0] = cNeg[nf][1] = 0.0f;
        }
        const int* catT = sCat + cur * BM;
        #pragma unroll
        for (int nf = 0; nf < 4; nf++) {
            int colL0 = wn * 32 + nf * 8 + lm * 2;
            int cj0 = catT[colL0], cj1 = catT[colL0 + 1];
            #pragma unroll
            for (int mf = 0; mf < 2; mf++) {
                #pragma unroll
                for (int h = 0; h < 2; h++) {
                    int rl  = wm * 32 + mf * 16 + h * 8 + l4;
                    int cir = ci[mf][h];
                    float s0 = acc[mf][nf][2 * h + 0] * INV_T;
                    float s1 = acc[mf][nf][2 * h + 1] * INV_T;
                    float e0 = __expf(s0 - M0);
                    float e1 = __expf(s1 - M0);
                    // row side (rows of block it)
                    if (cir != cj0)                   negs[mf][h] += e0;
                    else if (!diag || rl != colL0)    posm[mf][h] = fmaxf(posm[mf][h], s0);
                    if (cir != cj1)                   negs[mf][h] += e1;
                    else if (!diag || rl != colL0+1)  posm[mf][h] = fmaxf(posm[mf][h], s1);
                    // col side (rows of block jt, via symmetry) — ignored on diag
                    if (cir != cj0) cNeg[nf][0] += e0; else cPos[nf][0] = fmaxf(cPos[nf][0], s0);
                    if (cir != cj1) cNeg[nf][1] += e1; else cPos[nf][1] = fmaxf(cPos[nf][1], s1);
                }
            }
        }

        if (!diag) {
            // reduce col stats over l4 (lane bits 2..4), then over wm via smem
            #pragma unroll
            for (int nf = 0; nf < 4; nf++)
                #pragma unroll
                for (int s = 0; s < 2; s++) {
                    #pragma unroll
                    for (int o = 4; o <= 16; o <<= 1) {
                        cPos[nf][s] = fmaxf(cPos[nf][s],
                                            __shfl_xor_sync(0xFFFFFFFFu, cPos[nf][s], o));
                        cNeg[nf][s] += __shfl_xor_sync(0xFFFFFFFFu, cNeg[nf][s], o);
                    }
                }
            if (l4 == 0) {
                #pragma unroll
                for (int nf = 0; nf < 4; nf++)
                    #pragma unroll
                    for (int s = 0; s < 2; s++) {
                        int col = wn * 32 + nf * 8 + lm * 2 + s;
                        sRed[col * 8 + wm]     = cPos[nf][s];
                        sRed[col * 8 + 4 + wm] = cNeg[nf][s];
                    }
            }
            __syncthreads();
            if (tid < BM) {
                float cp = fmaxf(fmaxf(sRed[tid * 8 + 0], sRed[tid * 8 + 1]),
                                 fmaxf(sRed[tid * 8 + 2], sRed[tid * 8 + 3]));
                float cn = sRed[tid * 8 + 4] + sRed[tid * 8 + 5]
                         + sRed[tid * 8 + 6] + sRed[tid * 8 + 7];
                g_pos [it * BDIM + jt * BM + tid] = cp;
                g_negs[it * BDIM + jt * BM + tid] = cn;
            }
        }

        if (kk + 1 < end) cp_wait0();
        __syncthreads();
    }

    flush_rows(sRed, posm, negs, wm, wn, l4, lm, tid, curIt, segC);
    #undef TILE_OF
}

// ---------------------------------------------------------------------------
// Kernel 3: merge 64 contributor slots per row -> per-row loss -> block sums.
// ---------------------------------------------------------------------------
__global__ void k_merge() {
    int tid = threadIdx.x;                   // 128 threads, 64 blocks
    int r = blockIdx.x * BM + tid;
    float pm = -1e30f, ns = 0.0f;
    #pragma unroll 8
    for (int c = 0; c < NBLK; c++) {
        pm = fmaxf(pm, g_pos[c * BDIM + r]);
        ns += g_negs[c * BDIM + r];
    }
    float loss = 0.0f, cnt = 0.0f;
    if (pm > -1e29f && ns > 0.0f) {
        float lse = M0 + logf(expf(pm - M0) + ns);
        loss = lse - pm;
        cnt  = 1.0f;
    }
    __shared__ float ss[128], sc[128];
    ss[tid] = loss; sc[tid] = cnt;
    __syncthreads();
    for (int o = 64; o; o >>= 1) {
        if (tid < o) { ss[tid] += ss[tid + o]; sc[tid] += sc[tid + o]; }
        __syncthreads();
    }
    if (tid == 0) { g_psum[blockIdx.x] = ss[0]; g_pcnt[blockIdx.x] = sc[0]; }
}

__global__ void k_out(float* __restrict__ out) {
    int tid = threadIdx.x;                   // 64 threads
    __shared__ float ss[64], sc[64];
    ss[tid] = g_psum[tid]; sc[tid] = g_pcnt[tid];
    __syncthreads();
    for (int o = 32; o; o >>= 1) {
        if (tid < o) { ss[tid] += ss[tid + o]; sc[tid] += sc[tid + o]; }
        __syncthreads();
    }
    if (tid == 0) out[0] = (sc[0] > 0.0f) ? (ss[0] / sc[0]) : 0.0f;
}

// ---------------------------------------------------------------------------
extern "C" void kernel_launch(void* const* d_in, const int* in_sizes, int n_in,
                              void* d_out, int out_size) {
    const float* emb = (const float*)d_in[0];
    const int*   cat = (const int*)d_in[1];
    // d_in[2] = font_labels, unused

    cudaFuncSetAttribute(k_mma, cudaFuncAttributeMaxDynamicSharedMemorySize, SMEM_NEED);

    k_normalize<<<BDIM, 64>>>(emb);
    k_init<<<SLOTS / 512, 512>>>();

    k_mma<<<128, THREADS, SMEM_NEED>>>(cat);   // 32 pairs x 4 chunks = one wave

    k_merge<<<NBLK, BM>>>();
    k_out<<<1, 64>>>((float*)d_out);
}

// round 8
// speedup vs baseline: 15.2392x; 1.0955x over previous
#include <cuda_runtime.h>
#include <cuda_fp16.h>
#include <cstdint>

// B=8192, D=256, categories int32 on the wire.
#define BDIM 8192
#define DDIM 256
#define INV_T 1.4285714285714286f
#define M0    1.4285714285714286f

#define BM 128
#define NBLK 64                      // 8192 / 128 row blocks
#define THREADS 512                  // 16 warps: 4 in M x 4 in N
#define NTILES 2080                  // upper triangle incl. diagonal
#define GRID_MMA 148                 // one CTA per SM

#define STRIDE 528                   // bytes per tile row (256 fp16 = 512B + 16B pad)
#define TILEB  (128 * STRIDE)
#define A_OFF   0
#define B_OFF   TILEB                // two B buffers follow A
#define CAT_OFF (3 * TILEB)          // int[2][128]
#define RED_OFF (CAT_OFF + 1024)     // shared reduction buffer (8KB)
#define SMEM_NEED (RED_OFF + 8192 + 16)

#define SLOTS (NBLK * BDIM)

__device__ __half g_normh[BDIM * DDIM];
__device__ float  g_pos [SLOTS];     // P[c][r]: contributor col-block c, row r
__device__ float  g_negs[SLOTS];
__device__ float  g_psum[NBLK];
__device__ float  g_pcnt[NBLK];

// ---------------- helpers ----------------
__device__ __forceinline__ uint32_t smem_u32(const void* p) {
    uint32_t a;
    asm("{ .reg .u64 t; cvta.to.shared.u64 t, %1; cvt.u32.u64 %0, t; }" : "=r"(a) : "l"(p));
    return a;
}
__device__ __forceinline__ void cp16(uint32_t dst, const void* src) {
    asm volatile("cp.async.cg.shared.global [%0], [%1], 16;" :: "r"(dst), "l"(src));
}
__device__ __forceinline__ void cp_commit() {
    asm volatile("cp.async.commit_group;" ::: "memory");
}
__device__ __forceinline__ void cp_wait0() {
    asm volatile("cp.async.wait_group 0;" ::: "memory");
}
__device__ __forceinline__ void ldm4(uint32_t r[4], uint32_t addr) {
    asm volatile("ldmatrix.sync.aligned.m8n8.x4.shared.b16 {%0,%1,%2,%3}, [%4];"
                 : "=r"(r[0]), "=r"(r[1]), "=r"(r[2]), "=r"(r[3]) : "r"(addr));
}
__device__ __forceinline__ void mma16816(float d[4], const uint32_t a[4],
                                         uint32_t b0, uint32_t b1) {
    asm volatile(
        "mma.sync.aligned.m16n8k16.row.col.f32.f16.f16.f32 "
        "{%0,%1,%2,%3},{%4,%5,%6,%7},{%8,%9},{%0,%1,%2,%3};\n"
        : "+f"(d[0]), "+f"(d[1]), "+f"(d[2]), "+f"(d[3])
        : "r"(a[0]), "r"(a[1]), "r"(a[2]), "r"(a[3]), "r"(b0), "r"(b1));
}
__device__ __forceinline__ void tile_cp(uint32_t dstBase, const uint4* src, int rowStart) {
    int tid = threadIdx.x;
    #pragma unroll
    for (int t = 0; t < 8; t++) {
        int idx = tid + t * THREADS;       // 0..4095 16B chunks
        int r   = idx >> 5;
        int c   = idx & 31;
        cp16(dstBase + r * STRIDE + c * 16, src + (size_t)(rowStart + r) * 32 + c);
    }
}
// global tile index -> (it, jt): pair-major linearization of upper triangle
__device__ __forceinline__ void tile_of(int k, int& it, int& jt) {
    int p = k / 65;
    int q = k - p * 65;
    int n1 = NBLK - p;
    if (q < n1) { it = p;            jt = p + q; }
    else        { it = NBLK - 1 - p; jt = (NBLK - 1 - p) + (q - n1); }
}
// write accumulated row stats for segment (row block curIt) into slot column segC
__device__ __forceinline__ void flush_rows(float* sRed, float posm[2][2], float negs[2][2],
                                           int wm, int wn, int l4, int lm, int tid,
                                           int curIt, int segC) {
    #pragma unroll
    for (int mf = 0; mf < 2; mf++)
        #pragma unroll
        for (int h = 0; h < 2; h++)
            sRed[(wm * 32 + mf * 16 + h * 8 + l4) * 16 + wn * 4 + lm] = posm[mf][h];
    __syncthreads();
    if (tid < BM) {
        float p = -1e30f;
        #pragma unroll
        for (int x = 0; x < 16; x++) p = fmaxf(p, sRed[tid * 16 + x]);
        g_pos[segC * BDIM + curIt * BM + tid] = p;
    }
    __syncthreads();
    #pragma unroll
    for (int mf = 0; mf < 2; mf++)
        #pragma unroll
        for (int h = 0; h < 2; h++)
            sRed[(wm * 32 + mf * 16 + h * 8 + l4) * 16 + wn * 4 + lm] = negs[mf][h];
    __syncthreads();
    if (tid < BM) {
        float s = 0.0f;
        #pragma unroll
        for (int x = 0; x < 16; x++) s += sRed[tid * 16 + x];
        g_negs[segC * BDIM + curIt * BM + tid] = s;
    }
    __syncthreads();
}

// ---------------------------------------------------------------------------
// Kernel 0: scratch identity init.
// ---------------------------------------------------------------------------
__global__ void k_init() {
    int i = blockIdx.x * 512 + threadIdx.x;   // grid = SLOTS/512
    g_pos[i]  = -1e30f;
    g_negs[i] = 0.0f;
}

// ---------------------------------------------------------------------------
// Kernel 1: row L2-normalize, output fp16. One warp per row.
// ---------------------------------------------------------------------------
__global__ void k_normalize(const float* __restrict__ emb) {
    int lane = threadIdx.x & 31;
    int row  = blockIdx.x * 8 + (threadIdx.x >> 5);
    const float4* src = (const float4*)(emb + (size_t)row * DDIM);
    float4 v0 = src[lane];
    float4 v1 = src[lane + 32];
    float ss = v0.x*v0.x + v0.y*v0.y + v0.z*v0.z + v0.w*v0.w
             + v1.x*v1.x + v1.y*v1.y + v1.z*v1.z + v1.w*v1.w;
    #pragma unroll
    for (int o = 16; o; o >>= 1) ss += __shfl_xor_sync(0xFFFFFFFFu, ss, o);
    float inv = 1.0f / fmaxf(sqrtf(ss), 1e-12f);
    uint2* dst = (uint2*)(g_normh + (size_t)row * DDIM);
    __half2 a0 = __floats2half2_rn(v0.x * inv, v0.y * inv);
    __half2 a1 = __floats2half2_rn(v0.z * inv, v0.w * inv);
    __half2 b0 = __floats2half2_rn(v1.x * inv, v1.y * inv);
    __half2 b1 = __floats2half2_rn(v1.z * inv, v1.w * inv);
    uint2 oa, ob;
    oa.x = *reinterpret_cast<uint32_t*>(&a0);
    oa.y = *reinterpret_cast<uint32_t*>(&a1);
    ob.x = *reinterpret_cast<uint32_t*>(&b0);
    ob.y = *reinterpret_cast<uint32_t*>(&b1);
    dst[lane]      = oa;
    dst[lane + 32] = ob;
}

// ---------------------------------------------------------------------------
// Kernel 2: upper-triangle fp16 mma.sync sims GEMM, dual-sided epilogue.
// 2080 tiles cut into 148 contiguous chunks of the pair-major schedule.
// ---------------------------------------------------------------------------
__global__ void __launch_bounds__(THREADS, 1)
k_mma(const int* __restrict__ cat) {
    extern __shared__ char smRaw[];
    char* smBase = (char*)((((uintptr_t)smRaw) + 15) & ~(uintptr_t)15);
    const uint32_t base  = smem_u32(smBase);
    const uint32_t aAddr = base + A_OFF;
    const uint32_t bAddr = base + B_OFF;
    int*   sCat = (int*)(smBase + CAT_OFF);
    float* sRed = (float*)(smBase + RED_OFF);

    const int tid  = threadIdx.x;
    const int lane = tid & 31;
    const int warp = tid >> 5;
    const int wm = warp & 3;
    const int wn = warp >> 2;
    const int g  = lane >> 3;
    const int r7 = lane & 7;
    const int l4 = lane >> 2;
    const int lm = lane & 3;

    // balanced chunk schedule: 2080 = 148*14 + 8
    const int b     = blockIdx.x;
    const int start = b * 14 + min(b, 8);
    const int end   = start + 14 + (b < 8 ? 1 : 0);

    // per-lane ldmatrix base addresses
    uint32_t aPtr[2], bOff[2];
    #pragma unroll
    for (int mf = 0; mf < 2; mf++)
        aPtr[mf] = aAddr + (uint32_t)(wm * 32 + mf * 16 + (g & 1) * 8 + r7) * STRIDE
                         + (uint32_t)(g >> 1) * 16;
    #pragma unroll
    for (int np = 0; np < 2; np++)
        bOff[np] = (uint32_t)(wn * 32 + np * 16 + (g >> 1) * 8 + r7) * STRIDE
                 + (uint32_t)(g & 1) * 16;

    const uint4* src = (const uint4*)g_normh;

    // prologue
    int it0, jt0; tile_of(start, it0, jt0);
    tile_cp(aAddr, src, it0 * BM);
    tile_cp(bAddr, src, jt0 * BM);
    cp_commit();
    if (tid < BM) sCat[tid] = cat[jt0 * BM + tid];
    cp_wait0();
    __syncthreads();

    int curIt = it0, segC = jt0;
    int   ci[2][2];
    float posm[2][2], negs[2][2];
    #pragma unroll
    for (int mf = 0; mf < 2; mf++)
        #pragma unroll
        for (int h = 0; h < 2; h++) {
            ci[mf][h]   = cat[curIt * BM + wm * 32 + mf * 16 + h * 8 + l4];
            posm[mf][h] = -1e30f;
            negs[mf][h] = 0.0f;
        }

    for (int kk = start; kk < end; kk++) {
        int it, jt; tile_of(kk, it, jt);
        const int cur = (kk - start) & 1;

        if (it != curIt) {   // segment change: flush, reload A + row cats
            flush_rows(sRed, posm, negs, wm, wn, l4, lm, tid, curIt, segC);
            tile_cp(aAddr, src, it * BM);
            cp_commit();
            cp_wait0();
            __syncthreads();
            curIt = it; segC = jt;
            #pragma unroll
            for (int mf = 0; mf < 2; mf++)
                #pragma unroll
                for (int h = 0; h < 2; h++) {
                    ci[mf][h]   = cat[curIt * BM + wm * 32 + mf * 16 + h * 8 + l4];
                    posm[mf][h] = -1e30f;
                    negs[mf][h] = 0.0f;
                }
        }

        if (kk + 1 < end) {  // prefetch next B + its cats
            int itn, jtn; tile_of(kk + 1, itn, jtn);
            tile_cp(bAddr + (cur ^ 1) * TILEB, src, jtn * BM);
            cp_commit();
            if (tid < BM) sCat[(cur ^ 1) * BM + tid] = cat[jtn * BM + tid];
        }

        float acc[2][4][4];
        #pragma unroll
        for (int mf = 0; mf < 2; mf++)
            #pragma unroll
            for (int nf = 0; nf < 4; nf++)
                #pragma unroll
                for (int c = 0; c < 4; c++) acc[mf][nf][c] = 0.0f;

        const uint32_t bBuf = bAddr + cur * TILEB;
        #pragma unroll
        for (int kc = 0; kc < 16; kc++) {
            uint32_t af[2][4], bf[2][4];
            ldm4(af[0], aPtr[0] + kc * 32);
            ldm4(af[1], aPtr[1] + kc * 32);
            ldm4(bf[0], bBuf + bOff[0] + kc * 32);
            ldm4(bf[1], bBuf + bOff[1] + kc * 32);
            #pragma unroll
            for (int mf = 0; mf < 2; mf++)
                #pragma unroll
                for (int nf = 0; nf < 4; nf++)
                    mma16816(acc[mf][nf], af[mf],
                             bf[nf >> 1][(nf & 1) * 2], bf[nf >> 1][(nf & 1) * 2 + 1]);
        }

        // ---- fused dual-sided epilogue ----
        const bool diag = (it == jt);
        float cPos[4][2], cNeg[4][2];
        #pragma unroll
        for (int nf = 0; nf < 4; nf++) {
            cPos[nf][0] = cPos[nf][1] = -1e30f;
            cNeg[nf][0] = cNeg[nf][1] = 0.0f;
        }
        const int* catT = sCat + cur * BM;
        #pragma unroll
        for (int nf = 0; nf < 4; nf++) {
            int colL0 = wn * 32 + nf * 8 + lm * 2;
            int cj0 = catT[colL0], cj1 = catT[colL0 + 1];
            #pragma unroll
            for (int mf = 0; mf < 2; mf++) {
                #pragma unroll
                for (int h = 0; h < 2; h++) {
                    int rl  = wm * 32 + mf * 16 + h * 8 + l4;
                    int cir = ci[mf][h];
                    float s0 = acc[mf][nf][2 * h + 0] * INV_T;
                    float s1 = acc[mf][nf][2 * h + 1] * INV_T;
                    float e0 = __expf(s0 - M0);
                    float e1 = __expf(s1 - M0);
                    // row side (rows of block it)
                    if (cir != cj0)                   negs[mf][h] += e0;
                    else if (!diag || rl != colL0)    posm[mf][h] = fmaxf(posm[mf][h], s0);
                    if (cir != cj1)                   negs[mf][h] += e1;
                    else if (!diag || rl != colL0+1)  posm[mf][h] = fmaxf(posm[mf][h], s1);
                    // col side (rows of block jt, via symmetry) — ignored on diag
                    if (cir != cj0) cNeg[nf][0] += e0; else cPos[nf][0] = fmaxf(cPos[nf][0], s0);
                    if (cir != cj1) cNeg[nf][1] += e1; else cPos[nf][1] = fmaxf(cPos[nf][1], s1);
                }
            }
        }

        if (!diag) {
            #pragma unroll
            for (int nf = 0; nf < 4; nf++)
                #pragma unroll
                for (int s = 0; s < 2; s++) {
                    #pragma unroll
                    for (int o = 4; o <= 16; o <<= 1) {
                        cPos[nf][s] = fmaxf(cPos[nf][s],
                                            __shfl_xor_sync(0xFFFFFFFFu, cPos[nf][s], o));
                        cNeg[nf][s] += __shfl_xor_sync(0xFFFFFFFFu, cNeg[nf][s], o);
                    }
                }
            if (l4 == 0) {
                #pragma unroll
                for (int nf = 0; nf < 4; nf++)
                    #pragma unroll
                    for (int s = 0; s < 2; s++) {
                        int col = wn * 32 + nf * 8 + lm * 2 + s;
                        sRed[col * 8 + wm]     = cPos[nf][s];
                        sRed[col * 8 + 4 + wm] = cNeg[nf][s];
                    }
            }
            __syncthreads();
            if (tid < BM) {
                float cp = fmaxf(fmaxf(sRed[tid * 8 + 0], sRed[tid * 8 + 1]),
                                 fmaxf(sRed[tid * 8 + 2], sRed[tid * 8 + 3]));
                float cn = sRed[tid * 8 + 4] + sRed[tid * 8 + 5]
                         + sRed[tid * 8 + 6] + sRed[tid * 8 + 7];
                g_pos [it * BDIM + jt * BM + tid] = cp;
                g_negs[it * BDIM + jt * BM + tid] = cn;
            }
        }

        if (kk + 1 < end) cp_wait0();
        __syncthreads();
    }

    flush_rows(sRed, posm, negs, wm, wn, l4, lm, tid, curIt, segC);
}

// ---------------------------------------------------------------------------
// Kernel 3: merge 64 contributor slots per row -> per-row loss -> block sums.
// 512 threads: 4 partial-mergers per row for MLP.
// ---------------------------------------------------------------------------
__global__ void k_merge() {
    int tid  = threadIdx.x;                  // 512 threads, 64 blocks
    int row  = tid & 127;
    int part = tid >> 7;                     // 0..3
    int r = blockIdx.x * BM + row;
    float pm = -1e30f, ns = 0.0f;
    #pragma unroll
    for (int c = part * 16; c < part * 16 + 16; c++) {
        pm = fmaxf(pm, g_pos[c * BDIM + r]);
        ns += g_negs[c * BDIM + r];
    }
    __shared__ float sp[512], sn[512];
    sp[part * 128 + row] = pm;
    sn[part * 128 + row] = ns;
    __syncthreads();
    __shared__ float ss[128], sc[128];
    if (tid < 128) {
        float p = fmaxf(fmaxf(sp[tid], sp[128 + tid]),
                        fmaxf(sp[256 + tid], sp[384 + tid]));
        float n = sn[tid] + sn[128 + tid] + sn[256 + tid] + sn[384 + tid];
        float loss = 0.0f, cnt = 0.0f;
        if (p > -1e29f && n > 0.0f) {
            float lse = M0 + logf(expf(p - M0) + n);
            loss = lse - p;
            cnt  = 1.0f;
        }
        ss[tid] = loss; sc[tid] = cnt;
    }
    __syncthreads();
    for (int o = 64; o; o >>= 1) {
        if (tid < o) { ss[tid] += ss[tid + o]; sc[tid] += sc[tid + o]; }
        __syncthreads();
    }
    if (tid == 0) { g_psum[blockIdx.x] = ss[0]; g_pcnt[blockIdx.x] = sc[0]; }
}

__global__ void k_out(float* __restrict__ out) {
    int tid = threadIdx.x;                   // 64 threads
    __shared__ float ss[64], sc[64];
    ss[tid] = g_psum[tid]; sc[tid] = g_pcnt[tid];
    __syncthreads();
    for (int o = 32; o; o >>= 1) {
        if (tid < o) { ss[tid] += ss[tid + o]; sc[tid] += sc[tid + o]; }
        __syncthreads();
    }
    if (tid == 0) out[0] = (sc[0] > 0.0f) ? (ss[0] / sc[0]) : 0.0f;
}

// ---------------------------------------------------------------------------
extern "C" void kernel_launch(void* const* d_in, const int* in_sizes, int n_in,
                              void* d_out, int out_size) {
    const float* emb = (const float*)d_in[0];
    const int*   cat = (const int*)d_in[1];
    // d_in[2] = font_labels, unused

    cudaFuncSetAttribute(k_mma, cudaFuncAttributeMaxDynamicSharedMemorySize, SMEM_NEED);

    k_normalize<<<BDIM / 8, 256>>>(emb);
    k_init<<<SLOTS / 512, 512>>>();

    k_mma<<<GRID_MMA, THREADS, SMEM_NEED>>>(cat);

    k_merge<<<NBLK, 512>>>();
    k_out<<<1, 64>>>((float*)d_out);
}

// round 9
// speedup vs baseline: 17.0439x; 1.1184x over previous
#include <cuda_runtime.h>
#include <cuda_fp16.h>
#include <cstdint>

// B=8192, D=256, categories int32 on the wire.
#define BDIM 8192
#define DDIM 256
#define INV_T 1.4285714285714286f
#define M0    1.4285714285714286f

#define BM 128
#define NBLK 64
#define THREADS 512                  // 16 warps: 4 in M x 4 in N
#define GRID_MMA 148

#define TILEB 65536                  // 128 rows x 512 B (no pad; XOR-swizzled layout)
#define TILE_HALF 32768              // halves per tile image
#define A_OFF   0
#define B_OFF   TILEB
#define CAT_OFF (3 * TILEB)          // int[2][128]
#define RED_OFF (CAT_OFF + 1024)     // 8 KB
#define MBAR_OFF (RED_OFF + 8192)    // 3 mbarriers
#define SMEM_NEED (MBAR_OFF + 64)

#define SLOTS (NBLK * BDIM)

// g_normh holds 64 tile images of 64KB; element (rb, r, chunk c of 8 halves)
// lives at rb*32768 + r*256 + ((c&24)|((c^r)&7))*8  (halves)
__device__ __half g_normh[BDIM * DDIM];
__device__ float  g_pos [SLOTS];
__device__ float  g_negs[SLOTS];
__device__ float  g_psum[NBLK];
__device__ float  g_pcnt[NBLK];

// ---------------- helpers ----------------
__device__ __forceinline__ uint32_t smem_u32(const void* p) {
    uint32_t a;
    asm("{ .reg .u64 t; cvta.to.shared.u64 t, %1; cvt.u32.u64 %0, t; }" : "=r"(a) : "l"(p));
    return a;
}
__device__ __forceinline__ void mbar_init(uint32_t mbar, uint32_t cnt) {
    asm volatile("mbarrier.init.shared.b64 [%0], %1;" :: "r"(mbar), "r"(cnt) : "memory");
}
__device__ __forceinline__ void mbar_expect_tx(uint32_t mbar, uint32_t bytes) {
    asm volatile("mbarrier.arrive.expect_tx.shared.b64 _, [%0], %1;"
                 :: "r"(mbar), "r"(bytes) : "memory");
}
__device__ __forceinline__ void mbar_wait(uint32_t mbar, uint32_t parity) {
    asm volatile(
        "{\n\t.reg .pred P;\n\t"
        "WL_%=:\n\t"
        "mbarrier.try_wait.parity.acquire.cta.shared::cta.b64 P, [%0], %1, 0x989680;\n\t"
        "@P bra.uni WD_%=;\n\t"
        "bra.uni WL_%=;\n\t"
        "WD_%=:\n\t}"
        :: "r"(mbar), "r"(parity) : "memory");
}
__device__ __forceinline__ void bulk_cp(uint32_t dst, const void* src, uint32_t bytes,
                                        uint32_t mbar) {
    asm volatile(
        "cp.async.bulk.shared::cta.global.mbarrier::complete_tx::bytes [%0], [%1], %2, [%3];"
        :: "r"(dst), "l"(src), "r"(bytes), "r"(mbar) : "memory");
}
__device__ __forceinline__ void ldm4(uint32_t r[4], uint32_t addr) {
    asm volatile("ldmatrix.sync.aligned.m8n8.x4.shared.b16 {%0,%1,%2,%3}, [%4];"
                 : "=r"(r[0]), "=r"(r[1]), "=r"(r[2]), "=r"(r[3]) : "r"(addr));
}
__device__ __forceinline__ void mma16816(float d[4], const uint32_t a[4],
                                         uint32_t b0, uint32_t b1) {
    asm volatile(
        "mma.sync.aligned.m16n8k16.row.col.f32.f16.f16.f32 "
        "{%0,%1,%2,%3},{%4,%5,%6,%7},{%8,%9},{%0,%1,%2,%3};\n"
        : "+f"(d[0]), "+f"(d[1]), "+f"(d[2]), "+f"(d[3])
        : "r"(a[0]), "r"(a[1]), "r"(a[2]), "r"(a[3]), "r"(b0), "r"(b1));
}
__device__ __forceinline__ void tile_of(int k, int& it, int& jt) {
    int p = k / 65;
    int q = k - p * 65;
    int n1 = NBLK - p;
    if (q < n1) { it = p;            jt = p + q; }
    else        { it = NBLK - 1 - p; jt = (NBLK - 1 - p) + (q - n1); }
}
__device__ __forceinline__ void flush_rows(float* sRed, float posm[2][2], float negs[2][2],
                                           int wm, int wn, int l4, int lm, int tid,
                                           int curIt, int segC) {
    #pragma unroll
    for (int mf = 0; mf < 2; mf++)
        #pragma unroll
        for (int h = 0; h < 2; h++)
            sRed[(wm * 32 + mf * 16 + h * 8 + l4) * 16 + wn * 4 + lm] = posm[mf][h];
    __syncthreads();
    if (tid < BM) {
        float p = -1e30f;
        #pragma unroll
        for (int x = 0; x < 16; x++) p = fmaxf(p, sRed[tid * 16 + x]);
        g_pos[segC * BDIM + curIt * BM + tid] = p;
    }
    __syncthreads();
    #pragma unroll
    for (int mf = 0; mf < 2; mf++)
        #pragma unroll
        for (int h = 0; h < 2; h++)
            sRed[(wm * 32 + mf * 16 + h * 8 + l4) * 16 + wn * 4 + lm] = negs[mf][h];
    __syncthreads();
    if (tid < BM) {
        float s = 0.0f;
        #pragma unroll
        for (int x = 0; x < 16; x++) s += sRed[tid * 16 + x];
        g_negs[segC * BDIM + curIt * BM + tid] = s;
    }
    __syncthreads();
}

// ---------------------------------------------------------------------------
__global__ void k_init() {
    int i = blockIdx.x * 512 + threadIdx.x;
    g_pos[i]  = -1e30f;
    g_negs[i] = 0.0f;
}

// ---------------------------------------------------------------------------
// Kernel 1: L2-normalize + write XOR-swizzled tile images. One warp per row;
// lane handles one 16B chunk (8 halves).
// ---------------------------------------------------------------------------
__global__ void k_normalize(const float* __restrict__ emb) {
    int lane = threadIdx.x & 31;
    int row  = blockIdx.x * 8 + (threadIdx.x >> 5);
    const float4* src = (const float4*)(emb + (size_t)row * DDIM);
    float4 v0 = src[2 * lane];
    float4 v1 = src[2 * lane + 1];
    float ss = v0.x*v0.x + v0.y*v0.y + v0.z*v0.z + v0.w*v0.w
             + v1.x*v1.x + v1.y*v1.y + v1.z*v1.z + v1.w*v1.w;
    #pragma unroll
    for (int o = 16; o; o >>= 1) ss += __shfl_xor_sync(0xFFFFFFFFu, ss, o);
    float inv = 1.0f / fmaxf(sqrtf(ss), 1e-12f);
    __half2 a0 = __floats2half2_rn(v0.x * inv, v0.y * inv);
    __half2 a1 = __floats2half2_rn(v0.z * inv, v0.w * inv);
    __half2 b0 = __floats2half2_rn(v1.x * inv, v1.y * inv);
    __half2 b1 = __floats2half2_rn(v1.z * inv, v1.w * inv);
    uint4 o4;
    o4.x = *reinterpret_cast<uint32_t*>(&a0);
    o4.y = *reinterpret_cast<uint32_t*>(&a1);
    o4.z = *reinterpret_cast<uint32_t*>(&b0);
    o4.w = *reinterpret_cast<uint32_t*>(&b1);
    int rb = row >> 7, r = row & 127;
    int sw = (lane & 24) | ((lane ^ r) & 7);
    *(uint4*)(g_normh + (size_t)rb * TILE_HALF + r * 256 + sw * 8) = o4;
}

// ---------------------------------------------------------------------------
// Kernel 2: upper-triangle fp16 mma.sync GEMM, bulk-copied tiles, dual epilogue.
// ---------------------------------------------------------------------------
__global__ void __launch_bounds__(THREADS, 1)
k_mma(const int* __restrict__ cat) {
    extern __shared__ char smRaw[];
    char* smBase = (char*)((((uintptr_t)smRaw) + 15) & ~(uintptr_t)15);
    const uint32_t base  = smem_u32(smBase);
    const uint32_t aAddr = base + A_OFF;
    const uint32_t bAddr = base + B_OFF;
    const uint32_t mbA   = base + MBAR_OFF;
    const uint32_t mbB0  = base + MBAR_OFF + 8;
    const uint32_t mbB1  = base + MBAR_OFF + 16;
    int*   sCat = (int*)(smBase + CAT_OFF);
    float* sRed = (float*)(smBase + RED_OFF);

    const int tid  = threadIdx.x;
    const int lane = tid & 31;
    const int warp = tid >> 5;
    const int wm = warp & 3;
    const int wn = warp >> 2;
    const int g  = lane >> 3;
    const int r7 = lane & 7;
    const int l4 = lane >> 2;
    const int lm = lane & 3;

    // balanced chunk schedule: 2080 = 148*14 + 8
    const int b     = blockIdx.x;
    const int start = b * 14 + min(b, 8);
    const int end   = start + 14 + (b < 8 ? 1 : 0);

    if (tid == 0) { mbar_init(mbA, 1); mbar_init(mbB0, 1); mbar_init(mbB1, 1); }
    __syncthreads();

    // per-lane ldmatrix row bases (swizzled layout: addr = rowBase + sw(chunk)^*16)
    uint32_t aRow[2], bRow[2];
    #pragma unroll
    for (int mf = 0; mf < 2; mf++)
        aRow[mf] = aAddr + (uint32_t)(wm * 32 + mf * 16 + (g & 1) * 8 + r7) * 512;
    #pragma unroll
    for (int np = 0; np < 2; np++)
        bRow[np] = (uint32_t)(wn * 32 + np * 16 + (g >> 1) * 8 + r7) * 512;
    const int gh = g >> 1;       // A chunk parity
    const int gl = g & 1;        // B chunk parity

    // prologue: issue A + B0 bulk copies, load cats
    int it0, jt0; tile_of(start, it0, jt0);
    if (tid == 0) {
        mbar_expect_tx(mbA, TILEB);
        bulk_cp(aAddr, g_normh + (size_t)it0 * TILE_HALF, TILEB, mbA);
        mbar_expect_tx(mbB0, TILEB);
        bulk_cp(bAddr, g_normh + (size_t)jt0 * TILE_HALF, TILEB, mbB0);
    }
    if (tid < BM) sCat[tid] = cat[jt0 * BM + tid];

    int curIt = it0, segC = jt0;
    int   ci[2][2];
    float posm[2][2], negs[2][2];
    #pragma unroll
    for (int mf = 0; mf < 2; mf++)
        #pragma unroll
        for (int h = 0; h < 2; h++) {
            ci[mf][h]   = cat[curIt * BM + wm * 32 + mf * 16 + h * 8 + l4];
            posm[mf][h] = -1e30f;
            negs[mf][h] = 0.0f;
        }

    mbar_wait(mbA, 0);
    int pA = 1, pB0 = 0, pB1 = 0;
    __syncthreads();

    for (int kk = start; kk < end; kk++) {
        int it, jt; tile_of(kk, it, jt);
        const int cur = (kk - start) & 1;

        if (it != curIt) {   // segment change: flush, bulk-reload A + row cats
            flush_rows(sRed, posm, negs, wm, wn, l4, lm, tid, curIt, segC);
            if (tid == 0) {
                mbar_expect_tx(mbA, TILEB);
                bulk_cp(aAddr, g_normh + (size_t)it * TILE_HALF, TILEB, mbA);
            }
            __syncthreads();
            mbar_wait(mbA, pA); pA ^= 1;
            curIt = it; segC = jt;
            #pragma unroll
            for (int mf = 0; mf < 2; mf++)
                #pragma unroll
                for (int h = 0; h < 2; h++) {
                    ci[mf][h]   = cat[curIt * BM + wm * 32 + mf * 16 + h * 8 + l4];
                    posm[mf][h] = -1e30f;
                    negs[mf][h] = 0.0f;
                }
        }

        if (kk + 1 < end) {  // prefetch next B + its cats into buffer cur^1
            int itn, jtn; tile_of(kk + 1, itn, jtn);
            if (tid == 0) {
                uint32_t mb = (cur ^ 1) ? mbB1 : mbB0;
                mbar_expect_tx(mb, TILEB);
                bulk_cp(bAddr + (cur ^ 1) * TILEB, g_normh + (size_t)jtn * TILE_HALF,
                        TILEB, mb);
            }
            if (tid < BM) sCat[(cur ^ 1) * BM + tid] = cat[jtn * BM + tid];
        }

        // wait for buffer cur
        if (cur == 0) { mbar_wait(mbB0, pB0); pB0 ^= 1; }
        else          { mbar_wait(mbB1, pB1); pB1 ^= 1; }

        float acc[2][4][4];
        #pragma unroll
        for (int mf = 0; mf < 2; mf++)
            #pragma unroll
            for (int nf = 0; nf < 4; nf++)
                #pragma unroll
                for (int c = 0; c < 4; c++) acc[mf][nf][c] = 0.0f;

        const uint32_t bBuf = bAddr + cur * TILEB;
        #pragma unroll
        for (int kc = 0; kc < 16; kc++) {
            const int ca = kc * 2 + gh;
            const int cb = kc * 2 + gl;
            const uint32_t swa = (uint32_t)(((ca & 24) | ((ca ^ r7) & 7)) << 4);
            const uint32_t swb = (uint32_t)(((cb & 24) | ((cb ^ r7) & 7)) << 4);
            uint32_t af[2][4], bf[2][4];
            ldm4(af[0], aRow[0] + swa);
            ldm4(af[1], aRow[1] + swa);
            ldm4(bf[0], bBuf + bRow[0] + swb);
            ldm4(bf[1], bBuf + bRow[1] + swb);
            #pragma unroll
            for (int mf = 0; mf < 2; mf++)
                #pragma unroll
                for (int nf = 0; nf < 4; nf++)
                    mma16816(acc[mf][nf], af[mf],
                             bf[nf >> 1][(nf & 1) * 2], bf[nf >> 1][(nf & 1) * 2 + 1]);
        }

        // ---- fused dual-sided epilogue ----
        const bool diag = (it == jt);
        float cPos[4][2], cNeg[4][2];
        #pragma unroll
        for (int nf = 0; nf < 4; nf++) {
            cPos[nf][0] = cPos[nf][1] = -1e30f;
            cNeg[nf][0] = cNeg[nf][1] = 0.0f;
        }
        const int* catT = sCat + cur * BM;
        #pragma unroll
        for (int nf = 0; nf < 4; nf++) {
            int colL0 = wn * 32 + nf * 8 + lm * 2;
            int cj0 = catT[colL0], cj1 = catT[colL0 + 1];
            #pragma unroll
            for (int mf = 0; mf < 2; mf++) {
                #pragma unroll
                for (int h = 0; h < 2; h++) {
                    int rl  = wm * 32 + mf * 16 + h * 8 + l4;
                    int cir = ci[mf][h];
                    float s0 = acc[mf][nf][2 * h + 0] * INV_T;
                    float s1 = acc[mf][nf][2 * h + 1] * INV_T;
                    float e0 = __expf(s0 - M0);
                    float e1 = __expf(s1 - M0);
                    if (cir != cj0)                   negs[mf][h] += e0;
                    else if (!diag || rl != colL0)    posm[mf][h] = fmaxf(posm[mf][h], s0);
                    if (cir != cj1)                   negs[mf][h] += e1;
                    else if (!diag || rl != colL0+1)  posm[mf][h] = fmaxf(posm[mf][h], s1);
                    if (cir != cj0) cNeg[nf][0] += e0; else cPos[nf][0] = fmaxf(cPos[nf][0], s0);
                    if (cir != cj1) cNeg[nf][1] += e1; else cPos[nf][1] = fmaxf(cPos[nf][1], s1);
                }
            }
        }

        if (!diag) {
            #pragma unroll
            for (int nf = 0; nf < 4; nf++)
                #pragma unroll
                for (int s = 0; s < 2; s++) {
                    #pragma unroll
                    for (int o = 4; o <= 16; o <<= 1) {
                        cPos[nf][s] = fmaxf(cPos[nf][s],
                                            __shfl_xor_sync(0xFFFFFFFFu, cPos[nf][s], o));
                        cNeg[nf][s] += __shfl_xor_sync(0xFFFFFFFFu, cNeg[nf][s], o);
                    }
                }
            if (l4 == 0) {
                #pragma unroll
                for (int nf = 0; nf < 4; nf++)
                    #pragma unroll
                    for (int s = 0; s < 2; s++) {
                        int col = wn * 32 + nf * 8 + lm * 2 + s;
                        sRed[col * 8 + wm]     = cPos[nf][s];
                        sRed[col * 8 + 4 + wm] = cNeg[nf][s];
                    }
            }
            __syncthreads();
            if (tid < BM) {
                float cp = fmaxf(fmaxf(sRed[tid * 8 + 0], sRed[tid * 8 + 1]),
                                 fmaxf(sRed[tid * 8 + 2], sRed[tid * 8 + 3]));
                float cn = sRed[tid * 8 + 4] + sRed[tid * 8 + 5]
                         + sRed[tid * 8 + 6] + sRed[tid * 8 + 7];
                g_pos [it * BDIM + jt * BM + tid] = cp;
                g_negs[it * BDIM + jt * BM + tid] = cn;
            }
        }

        __syncthreads();   // all warps done with B[cur^1]'s prior contents + sCat
    }

    flush_rows(sRed, posm, negs, wm, wn, l4, lm, tid, curIt, segC);
}

// ---------------------------------------------------------------------------
// Kernel 3: merge 64 slots per row (8 partials x 8 slots) -> per-row loss.
// ---------------------------------------------------------------------------
__global__ void k_merge() {
    int tid  = threadIdx.x;                  // 1024 threads, 64 blocks
    int row  = tid & 127;
    int part = tid >> 7;                     // 0..7
    int r = blockIdx.x * BM + row;
    float pm = -1e30f, ns = 0.0f;
    #pragma unroll
    for (int c = part * 8; c < part * 8 + 8; c++) {
        pm = fmaxf(pm, g_pos[c * BDIM + r]);
        ns += g_negs[c * BDIM + r];
    }
    __shared__ float sp[1024], sn[1024];
    sp[part * 128 + row] = pm;
    sn[part * 128 + row] = ns;
    __syncthreads();
    __shared__ float ss[128], sc[128];
    if (tid < 128) {
        float p = -1e30f, n = 0.0f;
        #pragma unroll
        for (int x = 0; x < 8; x++) {
            p = fmaxf(p, sp[x * 128 + tid]);
            n += sn[x * 128 + tid];
        }
        float loss = 0.0f, cnt = 0.0f;
        if (p > -1e29f && n > 0.0f) {
            float lse = M0 + logf(expf(p - M0) + n);
            loss = lse - p;
            cnt  = 1.0f;
        }
        ss[tid] = loss; sc[tid] = cnt;
    }
    __syncthreads();
    for (int o = 64; o; o >>= 1) {
        if (tid < o) { ss[tid] += ss[tid + o]; sc[tid] += sc[tid + o]; }
        __syncthreads();
    }
    if (tid == 0) { g_psum[blockIdx.x] = ss[0]; g_pcnt[blockIdx.x] = sc[0]; }
}

__global__ void k_out(float* __restrict__ out) {
    int tid = threadIdx.x;                   // 64 threads
    __shared__ float ss[64], sc[64];
    ss[tid] = g_psum[tid]; sc[tid] = g_pcnt[tid];
    __syncthreads();
    for (int o = 32; o; o >>= 1) {
        if (tid < o) { ss[tid] += ss[tid + o]; sc[tid] += sc[tid + o]; }
        __syncthreads();
    }
    if (tid == 0) out[0] = (sc[0] > 0.0f) ? (ss[0] / sc[0]) : 0.0f;
}

// ---------------------------------------------------------------------------
extern "C" void kernel_launch(void* const* d_in, const int* in_sizes, int n_in,
                              void* d_out, int out_size) {
    const float* emb = (const float*)d_in[0];
    const int*   cat = (const int*)d_in[1];
    // d_in[2] = font_labels, unused

    cudaFuncSetAttribute(k_mma, cudaFuncAttributeMaxDynamicSharedMemorySize, SMEM_NEED);

    k_normalize<<<BDIM / 8, 256>>>(emb);
    k_init<<<SLOTS / 512, 512>>>();

    k_mma<<<GRID_MMA, THREADS, SMEM_NEED>>>(cat);

    k_merge<<<NBLK, 1024>>>();
    k_out<<<1, 64>>>((float*)d_out);
}

// round 10
// speedup vs baseline: 18.2532x; 1.0710x over previous
#include <cuda_runtime.h>
#include <cuda_fp16.h>
#include <cstdint>

// B=8192, D=256, categories int32 on the wire.
#define BDIM 8192
#define DDIM 256
#define INV_T 1.4285714285714286f
#define M0    1.4285714285714286f
#define C1    2.0609929155f          // INV_T * log2(e)
#define C2    2.0609929155f          // M0 * log2(e)
#define LN2   0.69314718056f

#define BM 128
#define NBLK 64
#define THREADS 512                  // 16 warps: 4 in M x 4 in N
#define GRID_MMA 148

#define TILEB 65536                  // 128 rows x 512 B (XOR-swizzled tile image)
#define TILE_HALF 32768
#define A_OFF   0
#define B_OFF   TILEB
#define CAT_OFF (3 * TILEB)          // int[2][128]
#define RED_OFF (CAT_OFF + 1024)     // 8 KB (two 4KB col-side buffers / flush scratch)
#define MBAR_OFF (RED_OFF + 8192)
#define SMEM_NEED (MBAR_OFF + 64)

#define SLOTS (NBLK * BDIM)
#define MERGE_BLKS 256

__device__ __half g_normh[BDIM * DDIM];
__device__ float  g_pos [SLOTS];
__device__ float  g_negs[SLOTS];
__device__ float  g_psum[MERGE_BLKS];
__device__ float  g_pcnt[MERGE_BLKS];

// ---------------- helpers ----------------
__device__ __forceinline__ uint32_t smem_u32(const void* p) {
    uint32_t a;
    asm("{ .reg .u64 t; cvta.to.shared.u64 t, %1; cvt.u32.u64 %0, t; }" : "=r"(a) : "l"(p));
    return a;
}
__device__ __forceinline__ float ex2f(float x) {
    float y;
    asm("ex2.approx.ftz.f32 %0, %1;" : "=f"(y) : "f"(x));
    return y;
}
__device__ __forceinline__ void mbar_init(uint32_t mbar, uint32_t cnt) {
    asm volatile("mbarrier.init.shared.b64 [%0], %1;" :: "r"(mbar), "r"(cnt) : "memory");
}
__device__ __forceinline__ void mbar_expect_tx(uint32_t mbar, uint32_t bytes) {
    asm volatile("mbarrier.arrive.expect_tx.shared.b64 _, [%0], %1;"
                 :: "r"(mbar), "r"(bytes) : "memory");
}
__device__ __forceinline__ void mbar_wait(uint32_t mbar, uint32_t parity) {
    asm volatile(
        "{\n\t.reg .pred P;\n\t"
        "WL_%=:\n\t"
        "mbarrier.try_wait.parity.acquire.cta.shared::cta.b64 P, [%0], %1, 0x989680;\n\t"
        "@P bra.uni WD_%=;\n\t"
        "bra.uni WL_%=;\n\t"
        "WD_%=:\n\t}"
        :: "r"(mbar), "r"(parity) : "memory");
}
__device__ __forceinline__ void bulk_cp(uint32_t dst, const void* src, uint32_t bytes,
                                        uint32_t mbar) {
    asm volatile(
        "cp.async.bulk.shared::cta.global.mbarrier::complete_tx::bytes [%0], [%1], %2, [%3];"
        :: "r"(dst), "l"(src), "r"(bytes), "r"(mbar) : "memory");
}
__device__ __forceinline__ void ldm4(uint32_t r[4], uint32_t addr) {
    asm volatile("ldmatrix.sync.aligned.m8n8.x4.shared.b16 {%0,%1,%2,%3}, [%4];"
                 : "=r"(r[0]), "=r"(r[1]), "=r"(r[2]), "=r"(r[3]) : "r"(addr));
}
__device__ __forceinline__ void mma16816(float d[4], const uint32_t a[4],
                                         uint32_t b0, uint32_t b1) {
    asm volatile(
        "mma.sync.aligned.m16n8k16.row.col.f32.f16.f16.f32 "
        "{%0,%1,%2,%3},{%4,%5,%6,%7},{%8,%9},{%0,%1,%2,%3};\n"
        : "+f"(d[0]), "+f"(d[1]), "+f"(d[2]), "+f"(d[3])
        : "r"(a[0]), "r"(a[1]), "r"(a[2]), "r"(a[3]), "r"(b0), "r"(b1));
}
__device__ __forceinline__ void tile_of(int k, int& it, int& jt) {
    int p = k / 65;
    int q = k - p * 65;
    int n1 = NBLK - p;
    if (q < n1) { it = p;            jt = p + q; }
    else        { it = NBLK - 1 - p; jt = (NBLK - 1 - p) + (q - n1); }
}
// write accumulated row stats (posm in t-space) into slot column segC
__device__ __forceinline__ void flush_rows(float* sRed, float posm[2][2], float negs[2][2],
                                           int wm, int wn, int l4, int lm, int tid,
                                           int curIt, int segC) {
    __syncthreads();   // prior col-side readers may still be on sRed (either half)
    #pragma unroll
    for (int mf = 0; mf < 2; mf++)
        #pragma unroll
        for (int h = 0; h < 2; h++)
            sRed[(wm * 32 + mf * 16 + h * 8 + l4) * 16 + wn * 4 + lm] = posm[mf][h];
    __syncthreads();
    if (tid < BM) {
        float p = -1e30f;
        #pragma unroll
        for (int x = 0; x < 16; x++) p = fmaxf(p, sRed[tid * 16 + x]);
        g_pos[segC * BDIM + curIt * BM + tid] = p * LN2 + M0;   // t -> sim
    }
    __syncthreads();
    #pragma unroll
    for (int mf = 0; mf < 2; mf++)
        #pragma unroll
        for (int h = 0; h < 2; h++)
            sRed[(wm * 32 + mf * 16 + h * 8 + l4) * 16 + wn * 4 + lm] = negs[mf][h];
    __syncthreads();
    if (tid < BM) {
        float s = 0.0f;
        #pragma unroll
        for (int x = 0; x < 16; x++) s += sRed[tid * 16 + x];
        g_negs[segC * BDIM + curIt * BM + tid] = s;
    }
    __syncthreads();
}

// ---------------------------------------------------------------------------
__global__ void k_init() {
    int i = blockIdx.x * 512 + threadIdx.x;     // grid = SLOTS/4/512 = 256
    ((float4*)g_pos)[i]  = make_float4(-1e30f, -1e30f, -1e30f, -1e30f);
    ((float4*)g_negs)[i] = make_float4(0.f, 0.f, 0.f, 0.f);
}

// ---------------------------------------------------------------------------
// Kernel 1: L2-normalize + write XOR-swizzled tile images. One warp per row.
// ---------------------------------------------------------------------------
__global__ void k_normalize(const float* __restrict__ emb) {
    int lane = threadIdx.x & 31;
    int row  = blockIdx.x * 8 + (threadIdx.x >> 5);
    const float4* src = (const float4*)(emb + (size_t)row * DDIM);
    float4 v0 = src[2 * lane];
    float4 v1 = src[2 * lane + 1];
    float ss = v0.x*v0.x + v0.y*v0.y + v0.z*v0.z + v0.w*v0.w
             + v1.x*v1.x + v1.y*v1.y + v1.z*v1.z + v1.w*v1.w;
    #pragma unroll
    for (int o = 16; o; o >>= 1) ss += __shfl_xor_sync(0xFFFFFFFFu, ss, o);
    float inv = 1.0f / fmaxf(sqrtf(ss), 1e-12f);
    __half2 a0 = __floats2half2_rn(v0.x * inv, v0.y * inv);
    __half2 a1 = __floats2half2_rn(v0.z * inv, v0.w * inv);
    __half2 b0 = __floats2half2_rn(v1.x * inv, v1.y * inv);
    __half2 b1 = __floats2half2_rn(v1.z * inv, v1.w * inv);
    uint4 o4;
    o4.x = *reinterpret_cast<uint32_t*>(&a0);
    o4.y = *reinterpret_cast<uint32_t*>(&a1);
    o4.z = *reinterpret_cast<uint32_t*>(&b0);
    o4.w = *reinterpret_cast<uint32_t*>(&b1);
    int rb = row >> 7, r = row & 127;
    int sw = (lane & 24) | ((lane ^ r) & 7);
    *(uint4*)(g_normh + (size_t)rb * TILE_HALF + r * 256 + sw * 8) = o4;
}

// ---------------------------------------------------------------------------
// Kernel 2: upper-triangle fp16 mma.sync GEMM, bulk-copied tiles, dual epilogue.
// ---------------------------------------------------------------------------
__global__ void __launch_bounds__(THREADS, 1)
k_mma(const int* __restrict__ cat) {
    extern __shared__ char smRaw[];
    char* smBase = (char*)((((uintptr_t)smRaw) + 15) & ~(uintptr_t)15);
    const uint32_t base  = smem_u32(smBase);
    const uint32_t aAddr = base + A_OFF;
    const uint32_t bAddr = base + B_OFF;
    const uint32_t mbA   = base + MBAR_OFF;
    const uint32_t mbB0  = base + MBAR_OFF + 8;
    const uint32_t mbB1  = base + MBAR_OFF + 16;
    int*   sCat = (int*)(smBase + CAT_OFF);
    float* sRed = (float*)(smBase + RED_OFF);

    const int tid  = threadIdx.x;
    const int lane = tid & 31;
    const int warp = tid >> 5;
    const int wm = warp & 3;
    const int wn = warp >> 2;
    const int g  = lane >> 3;
    const int r7 = lane & 7;
    const int l4 = lane >> 2;
    const int lm = lane & 3;

    // balanced chunk schedule: 2080 = 148*14 + 8
    const int b     = blockIdx.x;
    const int start = b * 14 + min(b, 8);
    const int end   = start + 14 + (b < 8 ? 1 : 0);

    if (tid == 0) { mbar_init(mbA, 1); mbar_init(mbB0, 1); mbar_init(mbB1, 1); }
    __syncthreads();

    uint32_t aRow[2], bRow[2];
    #pragma unroll
    for (int mf = 0; mf < 2; mf++)
        aRow[mf] = aAddr + (uint32_t)(wm * 32 + mf * 16 + (g & 1) * 8 + r7) * 512;
    #pragma unroll
    for (int np = 0; np < 2; np++)
        bRow[np] = (uint32_t)(wn * 32 + np * 16 + (g >> 1) * 8 + r7) * 512;
    const int gh = g >> 1;
    const int gl = g & 1;

    int it0, jt0; tile_of(start, it0, jt0);
    if (tid == 0) {
        mbar_expect_tx(mbA, TILEB);
        bulk_cp(aAddr, g_normh + (size_t)it0 * TILE_HALF, TILEB, mbA);
        mbar_expect_tx(mbB0, TILEB);
        bulk_cp(bAddr, g_normh + (size_t)jt0 * TILE_HALF, TILEB, mbB0);
    }
    if (tid < BM) sCat[tid] = cat[jt0 * BM + tid];

    int curIt = it0, segC = jt0;
    int   ci[2][2];
    float posm[2][2], negs[2][2];
    #pragma unroll
    for (int mf = 0; mf < 2; mf++)
        #pragma unroll
        for (int h = 0; h < 2; h++) {
            ci[mf][h]   = cat[curIt * BM + wm * 32 + mf * 16 + h * 8 + l4];
            posm[mf][h] = -1e30f;
            negs[mf][h] = 0.0f;
        }

    mbar_wait(mbA, 0);
    int pA = 1, pB0 = 0, pB1 = 0;
    __syncthreads();

    for (int kk = start; kk < end; kk++) {
        int it, jt; tile_of(kk, it, jt);
        const int cur = (kk - start) & 1;

        if (it != curIt) {
            flush_rows(sRed, posm, negs, wm, wn, l4, lm, tid, curIt, segC);
            if (tid == 0) {
                mbar_expect_tx(mbA, TILEB);
                bulk_cp(aAddr, g_normh + (size_t)it * TILE_HALF, TILEB, mbA);
            }
            __syncthreads();
            mbar_wait(mbA, pA); pA ^= 1;
            curIt = it; segC = jt;
            #pragma unroll
            for (int mf = 0; mf < 2; mf++)
                #pragma unroll
                for (int h = 0; h < 2; h++) {
                    ci[mf][h]   = cat[curIt * BM + wm * 32 + mf * 16 + h * 8 + l4];
                    posm[mf][h] = -1e30f;
                    negs[mf][h] = 0.0f;
                }
        }

        if (kk + 1 < end) {
            int itn, jtn; tile_of(kk + 1, itn, jtn);
            if (tid == 0) {
                uint32_t mb = (cur ^ 1) ? mbB1 : mbB0;
                mbar_expect_tx(mb, TILEB);
                bulk_cp(bAddr + (cur ^ 1) * TILEB, g_normh + (size_t)jtn * TILE_HALF,
                        TILEB, mb);
            }
            if (tid < BM) sCat[(cur ^ 1) * BM + tid] = cat[jtn * BM + tid];
        }

        if (cur == 0) { mbar_wait(mbB0, pB0); pB0 ^= 1; }
        else          { mbar_wait(mbB1, pB1); pB1 ^= 1; }

        float acc[2][4][4];
        #pragma unroll
        for (int mf = 0; mf < 2; mf++)
            #pragma unroll
            for (int nf = 0; nf < 4; nf++)
                #pragma unroll
                for (int c = 0; c < 4; c++) acc[mf][nf][c] = 0.0f;

        const uint32_t bBuf = bAddr + cur * TILEB;
        #pragma unroll
        for (int kc = 0; kc < 16; kc++) {
            const int ca = kc * 2 + gh;
            const int cb = kc * 2 + gl;
            const uint32_t swa = (uint32_t)(((ca & 24) | ((ca ^ r7) & 7)) << 4);
            const uint32_t swb = (uint32_t)(((cb & 24) | ((cb ^ r7) & 7)) << 4);
            uint32_t af[2][4], bf[2][4];
            ldm4(af[0], aRow[0] + swa);
            ldm4(af[1], aRow[1] + swa);
            ldm4(bf[0], bBuf + bRow[0] + swb);
            ldm4(bf[1], bBuf + bRow[1] + swb);
            #pragma unroll
            for (int mf = 0; mf < 2; mf++)
                #pragma unroll
                for (int nf = 0; nf < 4; nf++)
                    mma16816(acc[mf][nf], af[mf],
                             bf[nf >> 1][(nf & 1) * 2], bf[nf >> 1][(nf & 1) * 2 + 1]);
        }

        // ---- fused dual-sided epilogue, t-space: t = acc*C1 - C2, e = 2^t ----
        const bool diag = (it == jt);
        float cPos[4][2], cNeg[4][2];
        #pragma unroll
        for (int nf = 0; nf < 4; nf++) {
            cPos[nf][0] = cPos[nf][1] = -1e30f;
            cNeg[nf][0] = cNeg[nf][1] = 0.0f;
        }
        const int* catT = sCat + cur * BM;
        #pragma unroll
        for (int nf = 0; nf < 4; nf++) {
            int colL0 = wn * 32 + nf * 8 + lm * 2;
            int cj0 = catT[colL0], cj1 = catT[colL0 + 1];
            #pragma unroll
            for (int mf = 0; mf < 2; mf++) {
                #pragma unroll
                for (int h = 0; h < 2; h++) {
                    int rl  = wm * 32 + mf * 16 + h * 8 + l4;
                    int cir = ci[mf][h];
                    float t0 = fmaf(acc[mf][nf][2 * h + 0], C1, -C2);
                    float t1 = fmaf(acc[mf][nf][2 * h + 1], C1, -C2);
                    float e0 = ex2f(t0);
                    float e1 = ex2f(t1);
                    if (cir != cj0)                   negs[mf][h] += e0;
                    else if (!diag || rl != colL0)    posm[mf][h] = fmaxf(posm[mf][h], t0);
                    if (cir != cj1)                   negs[mf][h] += e1;
                    else if (!diag || rl != colL0+1)  posm[mf][h] = fmaxf(posm[mf][h], t1);
                    if (cir != cj0) cNeg[nf][0] += e0; else cPos[nf][0] = fmaxf(cPos[nf][0], t0);
                    if (cir != cj1) cNeg[nf][1] += e1; else cPos[nf][1] = fmaxf(cPos[nf][1], t1);
                }
            }
        }

        if (!diag) {
            #pragma unroll
            for (int nf = 0; nf < 4; nf++)
                #pragma unroll
                for (int s = 0; s < 2; s++) {
                    #pragma unroll
                    for (int o = 4; o <= 16; o <<= 1) {
                        cPos[nf][s] = fmaxf(cPos[nf][s],
                                            __shfl_xor_sync(0xFFFFFFFFu, cPos[nf][s], o));
                        cNeg[nf][s] += __shfl_xor_sync(0xFFFFFFFFu, cNeg[nf][s], o);
                    }
                }
            float* sRedC = sRed + cur * 1024;   // double-buffered 4KB halves
            if (l4 == 0) {
                #pragma unroll
                for (int nf = 0; nf < 4; nf++)
                    #pragma unroll
                    for (int s = 0; s < 2; s++) {
                        int col = wn * 32 + nf * 8 + lm * 2 + s;
                        sRedC[col * 8 + wm]     = cPos[nf][s];
                        sRedC[col * 8 + 4 + wm] = cNeg[nf][s];
                    }
            }
            __syncthreads();     // also the release point for B[cur] / sCat[cur]
            if (tid < BM) {
                float cp = fmaxf(fmaxf(sRedC[tid * 8 + 0], sRedC[tid * 8 + 1]),
                                 fmaxf(sRedC[tid * 8 + 2], sRedC[tid * 8 + 3]));
                float cn = sRedC[tid * 8 + 4] + sRedC[tid * 8 + 5]
                         + sRedC[tid * 8 + 6] + sRedC[tid * 8 + 7];
                g_pos [it * BDIM + jt * BM + tid] = cp * LN2 + M0;   // t -> sim
                g_negs[it * BDIM + jt * BM + tid] = cn;
            }
        } else {
            __syncthreads();     // release point on diagonal tiles
        }
    }

    flush_rows(sRed, posm, negs, wm, wn, l4, lm, tid, curIt, segC);
}

// ---------------------------------------------------------------------------
// Kernel 3: merge 64 slots per row -> per-row loss -> block partials.
// 256 blocks x 256 threads; block owns 32 rows; 8 partials x 8 slots per row.
// ---------------------------------------------------------------------------
__global__ void k_merge() {
    int tid  = threadIdx.x;
    int row  = tid & 31;
    int part = tid >> 5;                     // 0..7
    int r = blockIdx.x * 32 + row;
    float pm = -1e30f, ns = 0.0f;
    #pragma unroll
    for (int c = part * 8; c < part * 8 + 8; c++) {
        pm = fmaxf(pm, g_pos[c * BDIM + r]);
        ns += g_negs[c * BDIM + r];
    }
    __shared__ float sp[256], sn[256];
    sp[part * 32 + row] = pm;
    sn[part * 32 + row] = ns;
    __syncthreads();
    if (tid < 32) {
        float p = -1e30f, n = 0.0f;
        #pragma unroll
        for (int x = 0; x < 8; x++) {
            p = fmaxf(p, sp[x * 32 + tid]);
            n += sn[x * 32 + tid];
        }
        float loss = 0.0f, cnt = 0.0f;
        if (p > -1e29f && n > 0.0f) {
            float lse = M0 + logf(expf(p - M0) + n);
            loss = lse - p;
            cnt  = 1.0f;
        }
        #pragma unroll
        for (int o = 16; o; o >>= 1) {
            loss += __shfl_xor_sync(0xFFFFFFFFu, loss, o);
            cnt  += __shfl_xor_sync(0xFFFFFFFFu, cnt,  o);
        }
        if (tid == 0) { g_psum[blockIdx.x] = loss; g_pcnt[blockIdx.x] = cnt; }
    }
}

__global__ void k_out(float* __restrict__ out) {
    int tid = threadIdx.x;                   // 256 threads
    __shared__ float ss[256], sc[256];
    ss[tid] = g_psum[tid]; sc[tid] = g_pcnt[tid];
    __syncthreads();
    for (int o = 128; o; o >>= 1) {
        if (tid < o) { ss[tid] += ss[tid + o]; sc[tid] += sc[tid + o]; }
        __syncthreads();
    }
    if (tid == 0) out[0] = (sc[0] > 0.0f) ? (ss[0] / sc[0]) : 0.0f;
}

// ---------------------------------------------------------------------------
extern "C" void kernel_launch(void* const* d_in, const int* in_sizes, int n_in,
                              void* d_out, int out_size) {
    const float* emb = (const float*)d_in[0];
    const int*   cat = (const int*)d_in[1];
    // d_in[2] = font_labels, unused

    cudaFuncSetAttribute(k_mma, cudaFuncAttributeMaxDynamicSharedMemorySize, SMEM_NEED);

    k_normalize<<<BDIM / 8, 256>>>(emb);
    k_init<<<SLOTS / 4 / 512, 512>>>();

    k_mma<<<GRID_MMA, THREADS, SMEM_NEED>>>(cat);

    k_merge<<<MERGE_BLKS, 256>>>();
    k_out<<<1, 256>>>((float*)d_out);
}

// round 11
// speedup vs baseline: 18.3509x; 1.0053x over previous
#include <cuda_runtime.h>
#include <cuda_fp16.h>
#include <cstdint>

// B=8192, D=256, categories int32 on the wire.
#define BDIM 8192
#define DDIM 256
#define INV_T 1.4285714285714286f
#define M0    1.4285714285714286f
#define C1    2.0609929155f          // INV_T * log2(e)
#define C2    2.0609929155f          // M0 * log2(e)
#define LN2   0.69314718056f

#define BM 128
#define NBLK 64
#define THREADS 512                  // 16 warps: 4 in M x 4 in N
#define GRID_MMA 148

#define TILEB 65536                  // 128 rows x 512 B (XOR-swizzled tile image)
#define TILE_HALF 32768
#define A_OFF   0
#define B_OFF   TILEB
#define CAT_OFF (3 * TILEB)          // int[2][128]
#define RED_OFF (CAT_OFF + 1024)     // 8 KB (two 4KB col-side halves / flush scratch)
#define MBAR_OFF (RED_OFF + 8192)
#define SMEM_NEED (MBAR_OFF + 64)

#define SLOTS (NBLK * BDIM)          // 524288 floats per scratch array
#define MERGE_BLKS 512

__device__ __half g_normh[BDIM * DDIM];
__device__ float  g_pos [SLOTS];
__device__ float  g_negs[SLOTS];
__device__ float  g_psum[MERGE_BLKS];
__device__ float  g_pcnt[MERGE_BLKS];
__device__ int    g_sem;             // zero-init; self-resetting

// ---------------- helpers ----------------
__device__ __forceinline__ uint32_t smem_u32(const void* p) {
    uint32_t a;
    asm("{ .reg .u64 t; cvta.to.shared.u64 t, %1; cvt.u32.u64 %0, t; }" : "=r"(a) : "l"(p));
    return a;
}
__device__ __forceinline__ float ex2f(float x) {
    float y;
    asm("ex2.approx.ftz.f32 %0, %1;" : "=f"(y) : "f"(x));
    return y;
}
__device__ __forceinline__ void mbar_init(uint32_t mbar, uint32_t cnt) {
    asm volatile("mbarrier.init.shared.b64 [%0], %1;" :: "r"(mbar), "r"(cnt) : "memory");
}
__device__ __forceinline__ void mbar_expect_tx(uint32_t mbar, uint32_t bytes) {
    asm volatile("mbarrier.arrive.expect_tx.shared.b64 _, [%0], %1;"
                 :: "r"(mbar), "r"(bytes) : "memory");
}
__device__ __forceinline__ void mbar_wait(uint32_t mbar, uint32_t parity) {
    asm volatile(
        "{\n\t.reg .pred P;\n\t"
        "WL_%=:\n\t"
        "mbarrier.try_wait.parity.acquire.cta.shared::cta.b64 P, [%0], %1, 0x989680;\n\t"
        "@P bra.uni WD_%=;\n\t"
        "bra.uni WL_%=;\n\t"
        "WD_%=:\n\t}"
        :: "r"(mbar), "r"(parity) : "memory");
}
__device__ __forceinline__ void bulk_cp(uint32_t dst, const void* src, uint32_t bytes,
                                        uint32_t mbar) {
    asm volatile(
        "cp.async.bulk.shared::cta.global.mbarrier::complete_tx::bytes [%0], [%1], %2, [%3];"
        :: "r"(dst), "l"(src), "r"(bytes), "r"(mbar) : "memory");
}
__device__ __forceinline__ void ldm4(uint32_t r[4], uint32_t addr) {
    asm volatile("ldmatrix.sync.aligned.m8n8.x4.shared.b16 {%0,%1,%2,%3}, [%4];"
                 : "=r"(r[0]), "=r"(r[1]), "=r"(r[2]), "=r"(r[3]) : "r"(addr));
}
__device__ __forceinline__ void mma16816(float d[4], const uint32_t a[4],
                                         uint32_t b0, uint32_t b1) {
    asm volatile(
        "mma.sync.aligned.m16n8k16.row.col.f32.f16.f16.f32 "
        "{%0,%1,%2,%3},{%4,%5,%6,%7},{%8,%9},{%0,%1,%2,%3};\n"
        : "+f"(d[0]), "+f"(d[1]), "+f"(d[2]), "+f"(d[3])
        : "r"(a[0]), "r"(a[1]), "r"(a[2]), "r"(a[3]), "r"(b0), "r"(b1));
}
__device__ __forceinline__ void tile_of(int k, int& it, int& jt) {
    int p = k / 65;
    int q = k - p * 65;
    int n1 = NBLK - p;
    if (q < n1) { it = p;            jt = p + q; }
    else        { it = NBLK - 1 - p; jt = (NBLK - 1 - p) + (q - n1); }
}
__device__ __forceinline__ void flush_rows(float* sRed, float posm[2][2], float negs[2][2],
                                           int wm, int wn, int l4, int lm, int tid,
                                           int curIt, int segC) {
    __syncthreads();
    #pragma unroll
    for (int mf = 0; mf < 2; mf++)
        #pragma unroll
        for (int h = 0; h < 2; h++)
            sRed[(wm * 32 + mf * 16 + h * 8 + l4) * 16 + wn * 4 + lm] = posm[mf][h];
    __syncthreads();
    if (tid < BM) {
        float p = -1e30f;
        #pragma unroll
        for (int x = 0; x < 16; x++) p = fmaxf(p, sRed[tid * 16 + x]);
        g_pos[segC * BDIM + curIt * BM + tid] = p * LN2 + M0;   // t -> sim
    }
    __syncthreads();
    #pragma unroll
    for (int mf = 0; mf < 2; mf++)
        #pragma unroll
        for (int h = 0; h < 2; h++)
            sRed[(wm * 32 + mf * 16 + h * 8 + l4) * 16 + wn * 4 + lm] = negs[mf][h];
    __syncthreads();
    if (tid < BM) {
        float s = 0.0f;
        #pragma unroll
        for (int x = 0; x < 16; x++) s += sRed[tid * 16 + x];
        g_negs[segC * BDIM + curIt * BM + tid] = s;
    }
    __syncthreads();
}

// ---------------------------------------------------------------------------
// Kernel 1: L2-normalize + swizzled tile images + scratch identity init.
// 1024 blocks x 256 threads: warp-per-row normalize; thread-indexed init.
// ---------------------------------------------------------------------------
__global__ void k_prep(const float* __restrict__ emb) {
    int lane = threadIdx.x & 31;
    int row  = blockIdx.x * 8 + (threadIdx.x >> 5);
    const float4* src = (const float4*)(emb + (size_t)row * DDIM);
    float4 v0 = src[2 * lane];
    float4 v1 = src[2 * lane + 1];
    float ss = v0.x*v0.x + v0.y*v0.y + v0.z*v0.z + v0.w*v0.w
             + v1.x*v1.x + v1.y*v1.y + v1.z*v1.z + v1.w*v1.w;
    #pragma unroll
    for (int o = 16; o; o >>= 1) ss += __shfl_xor_sync(0xFFFFFFFFu, ss, o);
    float inv = 1.0f / fmaxf(sqrtf(ss), 1e-12f);
    __half2 a0 = __floats2half2_rn(v0.x * inv, v0.y * inv);
    __half2 a1 = __floats2half2_rn(v0.z * inv, v0.w * inv);
    __half2 b0 = __floats2half2_rn(v1.x * inv, v1.y * inv);
    __half2 b1 = __floats2half2_rn(v1.z * inv, v1.w * inv);
    uint4 o4;
    o4.x = *reinterpret_cast<uint32_t*>(&a0);
    o4.y = *reinterpret_cast<uint32_t*>(&a1);
    o4.z = *reinterpret_cast<uint32_t*>(&b0);
    o4.w = *reinterpret_cast<uint32_t*>(&b1);
    int rb = row >> 7, r = row & 127;
    int sw = (lane & 24) | ((lane ^ r) & 7);
    *(uint4*)(g_normh + (size_t)rb * TILE_HALF + r * 256 + sw * 8) = o4;

    // scratch identity init: 262144 threads cover 2 x 131072 float4 slots
    int i = blockIdx.x * 256 + threadIdx.x;
    if (i < SLOTS / 4) ((float4*)g_pos)[i] = make_float4(-1e30f, -1e30f, -1e30f, -1e30f);
    else               ((float4*)g_negs)[i - SLOTS / 4] = make_float4(0.f, 0.f, 0.f, 0.f);
}

// ---------------------------------------------------------------------------
// Kernel 2: upper-triangle fp16 mma.sync GEMM, bulk-copied tiles, dual epilogue.
// (unchanged from R10)
// ---------------------------------------------------------------------------
__global__ void __launch_bounds__(THREADS, 1)
k_mma(const int* __restrict__ cat) {
    extern __shared__ char smRaw[];
    char* smBase = (char*)((((uintptr_t)smRaw) + 15) & ~(uintptr_t)15);
    const uint32_t base  = smem_u32(smBase);
    const uint32_t aAddr = base + A_OFF;
    const uint32_t bAddr = base + B_OFF;
    const uint32_t mbA   = base + MBAR_OFF;
    const uint32_t mbB0  = base + MBAR_OFF + 8;
    const uint32_t mbB1  = base + MBAR_OFF + 16;
    int*   sCat = (int*)(smBase + CAT_OFF);
    float* sRed = (float*)(smBase + RED_OFF);

    const int tid  = threadIdx.x;
    const int lane = tid & 31;
    const int warp = tid >> 5;
    const int wm = warp & 3;
    const int wn = warp >> 2;
    const int g  = lane >> 3;
    const int r7 = lane & 7;
    const int l4 = lane >> 2;
    const int lm = lane & 3;

    const int b     = blockIdx.x;
    const int start = b * 14 + min(b, 8);
    const int end   = start + 14 + (b < 8 ? 1 : 0);

    if (tid == 0) { mbar_init(mbA, 1); mbar_init(mbB0, 1); mbar_init(mbB1, 1); }
    __syncthreads();

    uint32_t aRow[2], bRow[2];
    #pragma unroll
    for (int mf = 0; mf < 2; mf++)
        aRow[mf] = aAddr + (uint32_t)(wm * 32 + mf * 16 + (g & 1) * 8 + r7) * 512;
    #pragma unroll
    for (int np = 0; np < 2; np++)
        bRow[np] = (uint32_t)(wn * 32 + np * 16 + (g >> 1) * 8 + r7) * 512;
    const int gh = g >> 1;
    const int gl = g & 1;

    int it0, jt0; tile_of(start, it0, jt0);
    if (tid == 0) {
        mbar_expect_tx(mbA, TILEB);
        bulk_cp(aAddr, g_normh + (size_t)it0 * TILE_HALF, TILEB, mbA);
        mbar_expect_tx(mbB0, TILEB);
        bulk_cp(bAddr, g_normh + (size_t)jt0 * TILE_HALF, TILEB, mbB0);
    }
    if (tid < BM) sCat[tid] = cat[jt0 * BM + tid];

    int curIt = it0, segC = jt0;
    int   ci[2][2];
    float posm[2][2], negs[2][2];
    #pragma unroll
    for (int mf = 0; mf < 2; mf++)
        #pragma unroll
        for (int h = 0; h < 2; h++) {
            ci[mf][h]   = cat[curIt * BM + wm * 32 + mf * 16 + h * 8 + l4];
            posm[mf][h] = -1e30f;
            negs[mf][h] = 0.0f;
        }

    mbar_wait(mbA, 0);
    int pA = 1, pB0 = 0, pB1 = 0;
    __syncthreads();

    for (int kk = start; kk < end; kk++) {
        int it, jt; tile_of(kk, it, jt);
        const int cur = (kk - start) & 1;

        if (it != curIt) {
            flush_rows(sRed, posm, negs, wm, wn, l4, lm, tid, curIt, segC);
            if (tid == 0) {
                mbar_expect_tx(mbA, TILEB);
                bulk_cp(aAddr, g_normh + (size_t)it * TILE_HALF, TILEB, mbA);
            }
            __syncthreads();
            mbar_wait(mbA, pA); pA ^= 1;
            curIt = it; segC = jt;
            #pragma unroll
            for (int mf = 0; mf < 2; mf++)
                #pragma unroll
                for (int h = 0; h < 2; h++) {
                    ci[mf][h]   = cat[curIt * BM + wm * 32 + mf * 16 + h * 8 + l4];
                    posm[mf][h] = -1e30f;
                    negs[mf][h] = 0.0f;
                }
        }

        if (kk + 1 < end) {
            int itn, jtn; tile_of(kk + 1, itn, jtn);
            if (tid == 0) {
                uint32_t mb = (cur ^ 1) ? mbB1 : mbB0;
                mbar_expect_tx(mb, TILEB);
                bulk_cp(bAddr + (cur ^ 1) * TILEB, g_normh + (size_t)jtn * TILE_HALF,
                        TILEB, mb);
            }
            if (tid < BM) sCat[(cur ^ 1) * BM + tid] = cat[jtn * BM + tid];
        }

        if (cur == 0) { mbar_wait(mbB0, pB0); pB0 ^= 1; }
        else          { mbar_wait(mbB1, pB1); pB1 ^= 1; }

        float acc[2][4][4];
        #pragma unroll
        for (int mf = 0; mf < 2; mf++)
            #pragma unroll
            for (int nf = 0; nf < 4; nf++)
                #pragma unroll
                for (int c = 0; c < 4; c++) acc[mf][nf][c] = 0.0f;

        const uint32_t bBuf = bAddr + cur * TILEB;
        #pragma unroll
        for (int kc = 0; kc < 16; kc++) {
            const int ca = kc * 2 + gh;
            const int cb = kc * 2 + gl;
            const uint32_t swa = (uint32_t)(((ca & 24) | ((ca ^ r7) & 7)) << 4);
            const uint32_t swb = (uint32_t)(((cb & 24) | ((cb ^ r7) & 7)) << 4);
            uint32_t af[2][4], bf[2][4];
            ldm4(af[0], aRow[0] + swa);
            ldm4(af[1], aRow[1] + swa);
            ldm4(bf[0], bBuf + bRow[0] + swb);
            ldm4(bf[1], bBuf + bRow[1] + swb);
            #pragma unroll
            for (int mf = 0; mf < 2; mf++)
                #pragma unroll
                for (int nf = 0; nf < 4; nf++)
                    mma16816(acc[mf][nf], af[mf],
                             bf[nf >> 1][(nf & 1) * 2], bf[nf >> 1][(nf & 1) * 2 + 1]);
        }

        const bool diag = (it == jt);
        float cPos[4][2], cNeg[4][2];
        #pragma unroll
        for (int nf = 0; nf < 4; nf++) {
            cPos[nf][0] = cPos[nf][1] = -1e30f;
            cNeg[nf][0] = cNeg[nf][1] = 0.0f;
        }
        const int* catT = sCat + cur * BM;
        #pragma unroll
        for (int nf = 0; nf < 4; nf++) {
            int colL0 = wn * 32 + nf * 8 + lm * 2;
            int cj0 = catT[colL0], cj1 = catT[colL0 + 1];
            #pragma unroll
            for (int mf = 0; mf < 2; mf++) {
                #pragma unroll
                for (int h = 0; h < 2; h++) {
                    int rl  = wm * 32 + mf * 16 + h * 8 + l4;
                    int cir = ci[mf][h];
                    float t0 = fmaf(acc[mf][nf][2 * h + 0], C1, -C2);
                    float t1 = fmaf(acc[mf][nf][2 * h + 1], C1, -C2);
                    float e0 = ex2f(t0);
                    float e1 = ex2f(t1);
                    if (cir != cj0)                   negs[mf][h] += e0;
                    else if (!diag || rl != colL0)    posm[mf][h] = fmaxf(posm[mf][h], t0);
                    if (cir != cj1)                   negs[mf][h] += e1;
                    else if (!diag || rl != colL0+1)  posm[mf][h] = fmaxf(posm[mf][h], t1);
                    if (cir != cj0) cNeg[nf][0] += e0; else cPos[nf][0] = fmaxf(cPos[nf][0], t0);
                    if (cir != cj1) cNeg[nf][1] += e1; else cPos[nf][1] = fmaxf(cPos[nf][1], t1);
                }
            }
        }

        if (!diag) {
            #pragma unroll
            for (int nf = 0; nf < 4; nf++)
                #pragma unroll
                for (int s = 0; s < 2; s++) {
                    #pragma unroll
                    for (int o = 4; o <= 16; o <<= 1) {
                        cPos[nf][s] = fmaxf(cPos[nf][s],
                                            __shfl_xor_sync(0xFFFFFFFFu, cPos[nf][s], o));
                        cNeg[nf][s] += __shfl_xor_sync(0xFFFFFFFFu, cNeg[nf][s], o);
                    }
                }
            float* sRedC = sRed + cur * 1024;
            if (l4 == 0) {
                #pragma unroll
                for (int nf = 0; nf < 4; nf++)
                    #pragma unroll
                    for (int s = 0; s < 2; s++) {
                        int col = wn * 32 + nf * 8 + lm * 2 + s;
                        sRedC[col * 8 + wm]     = cPos[nf][s];
                        sRedC[col * 8 + 4 + wm] = cNeg[nf][s];
                    }
            }
            __syncthreads();
            if (tid < BM) {
                float cp = fmaxf(fmaxf(sRedC[tid * 8 + 0], sRedC[tid * 8 + 1]),
                                 fmaxf(sRedC[tid * 8 + 2], sRedC[tid * 8 + 3]));
                float cn = sRedC[tid * 8 + 4] + sRedC[tid * 8 + 5]
                         + sRedC[tid * 8 + 6] + sRedC[tid * 8 + 7];
                g_pos [it * BDIM + jt * BM + tid] = cp * LN2 + M0;
                g_negs[it * BDIM + jt * BM + tid] = cn;
            }
        } else {
            __syncthreads();
        }
    }

    flush_rows(sRed, posm, negs, wm, wn, l4, lm, tid, curIt, segC);
}

// ---------------------------------------------------------------------------
// Kernel 3: merge 64 slots per row -> per-row loss -> block partials -> final
// mean via last-block reduction (threadfence + atomic counter, deterministic).
// 512 blocks x 256 threads; block owns 16 rows; 16 partials x 4 slots per row.
// ---------------------------------------------------------------------------
__global__ void k_merge(float* __restrict__ out) {
    int tid  = threadIdx.x;
    int row  = tid & 15;
    int part = tid >> 4;                     // 0..15
    int r = blockIdx.x * 16 + row;
    float pm = -1e30f, ns = 0.0f;
    #pragma unroll
    for (int c = part * 4; c < part * 4 + 4; c++) {
        pm = fmaxf(pm, g_pos[c * BDIM + r]);
        ns += g_negs[c * BDIM + r];
    }
    __shared__ float sp[256], sn[256];
    sp[tid] = pm; sn[tid] = ns;              // [part][row]
    __syncthreads();
    if (tid < 16) {
        float p = -1e30f, n = 0.0f;
        #pragma unroll
        for (int x = 0; x < 16; x++) {
            p = fmaxf(p, sp[x * 16 + tid]);
            n += sn[x * 16 + tid];
        }
        float loss = 0.0f, cnt = 0.0f;
        if (p > -1e29f && n > 0.0f) {
            float lse = M0 + logf(expf(p - M0) + n);
            loss = lse - p;
            cnt  = 1.0f;
        }
        #pragma unroll
        for (int o = 8; o; o >>= 1) {
            loss += __shfl_xor_sync(0x0000FFFFu, loss, o);
            cnt  += __shfl_xor_sync(0x0000FFFFu, cnt,  o);
        }
        if (tid == 0) { g_psum[blockIdx.x] = loss; g_pcnt[blockIdx.x] = cnt; }
    }
    // last-block final reduction
    __threadfence();
    __shared__ int isLast;
    if (tid == 0) isLast = (atomicAdd(&g_sem, 1) == MERGE_BLKS - 1);
    __syncthreads();
    if (isLast) {
        float s = 0.0f, c = 0.0f;
        #pragma unroll
        for (int i = tid; i < MERGE_BLKS; i += 256) {
            s += __ldcg(&g_psum[i]);
            c += __ldcg(&g_pcnt[i]);
        }
        __shared__ float ss[256], sc[256];
        ss[tid] = s; sc[tid] = c;
        __syncthreads();
        for (int o = 128; o; o >>= 1) {
            if (tid < o) { ss[tid] += ss[tid + o]; sc[tid] += sc[tid + o]; }
            __syncthreads();
        }
        if (tid == 0) {
            out[0] = (sc[0] > 0.0f) ? (ss[0] / sc[0]) : 0.0f;
            g_sem = 0;                       // reset for next graph replay
        }
    }
}

// ---------------------------------------------------------------------------
extern "C" void kernel_launch(void* const* d_in, const int* in_sizes, int n_in,
                              void* d_out, int out_size) {
    const float* emb = (const float*)d_in[0];
    const int*   cat = (const int*)d_in[1];
    // d_in[2] = font_labels, unused

    cudaFuncSetAttribute(k_mma, cudaFuncAttributeMaxDynamicSharedMemorySize, SMEM_NEED);

    k_prep<<<BDIM / 8, 256>>>(emb);
    k_mma<<<GRID_MMA, THREADS, SMEM_NEED>>>(cat);
    k_merge<<<MERGE_BLKS, 256>>>((float*)d_out);
}